// round 13
// baseline (speedup 1.0000x reference)
#include <cuda_runtime.h>
#include <cuda_fp16.h>
#include <cstdint>

#define N_EMBD 2048
#define N_HEAD 16
#define HEAD_DIM 128
#define BATCH 2
#define SEQ 2048

// ---------------- scratch ----------------------------------------------------
__device__ __half g_x_h[(size_t)BATCH * SEQ * N_EMBD];
__device__ __half g_wqkvT[(size_t)3 * N_EMBD * N_EMBD];
__device__ __half g_wprojT[(size_t)N_EMBD * N_EMBD];
__device__ __half g_qkv_h[(size_t)BATCH * SEQ * 3 * N_EMBD];
__device__ __half g_attn_h[(size_t)BATCH * SEQ * N_EMBD];

// ---------------- PTX helpers -------------------------------------------------
__device__ __forceinline__ uint32_t smem_u32(const void* p) {
    return (uint32_t)__cvta_generic_to_shared(p);
}
__device__ __forceinline__ void ldsm_x4(uint32_t* r, uint32_t addr) {
    asm volatile("ldmatrix.sync.aligned.m8n8.x4.shared.b16 {%0,%1,%2,%3}, [%4];"
                 : "=r"(r[0]), "=r"(r[1]), "=r"(r[2]), "=r"(r[3]) : "r"(addr));
}
__device__ __forceinline__ void ldsm_x4_t(uint32_t* r, uint32_t addr) {
    asm volatile("ldmatrix.sync.aligned.m8n8.x4.trans.shared.b16 {%0,%1,%2,%3}, [%4];"
                 : "=r"(r[0]), "=r"(r[1]), "=r"(r[2]), "=r"(r[3]) : "r"(addr));
}
__device__ __forceinline__ void mma_f16(float* d, const uint32_t* a, const uint32_t* b) {
    asm volatile(
        "mma.sync.aligned.m16n8k16.row.col.f32.f16.f16.f32 "
        "{%0,%1,%2,%3},{%4,%5,%6,%7},{%8,%9},{%0,%1,%2,%3};"
        : "+f"(d[0]), "+f"(d[1]), "+f"(d[2]), "+f"(d[3])
        : "r"(a[0]), "r"(a[1]), "r"(a[2]), "r"(a[3]), "r"(b[0]), "r"(b[1]));
}
__device__ __forceinline__ void cp16(uint32_t dst, const void* src) {
    asm volatile("cp.async.cg.shared.global [%0], [%1], 16;" :: "r"(dst), "l"(src));
}
__device__ __forceinline__ void cp_commit() {
    asm volatile("cp.async.commit_group;" ::: "memory");
}
template <int W> __device__ __forceinline__ void cp_wait() {
    asm volatile("cp.async.wait_group %0;" :: "n"(W) : "memory");
}
__device__ __forceinline__ uint32_t packh(__half a, __half b) {
    __half2 t; t.x = a; t.y = b;
    uint32_t u; *(__half2*)&u = t; return u;
}

// ---------------- plain fp16 GEMM, warp tile 64x64, CTA 128x256 ---------------
// BK=32, 3-stage, 1 sync/tile, 1 CTA/SM. A:[M][K], B:[N][K], 64B smem rows.
template <bool WF32>
__global__ __launch_bounds__(256) void gemm_big(
    const __half* __restrict__ A, const __half* __restrict__ B,
    const float* __restrict__ bias,
    float* __restrict__ C, __half* __restrict__ Ch,
    int K, int lda, int ldb, int ldc)
{
    extern __shared__ char smem[];
    const int tid = threadIdx.x;
    const int m0 = blockIdx.y * 128, n0 = blockIdx.x * 256;
    const int nt = K >> 5;

    const uint32_t S0 = smem_u32(smem);
    const int arow = tid >> 1, ac0 = (tid & 1) * 2;

    auto copy_stage = [&](int kt) {
        const uint32_t base = S0 + (uint32_t)(kt % 3) * 24576;
        const int k0 = kt << 5;
        // A: 128 rows x 64B
#pragma unroll
        for (int j = 0; j < 2; ++j) {
            int c = ac0 + j;
            cp16(base + arow * 64 + ((c ^ ((arow >> 1) & 3)) << 4),
                 A + (size_t)(m0 + arow) * lda + k0 + c * 8);
        }
        // B: 256 rows x 64B (one row per thread, 4 chunks)
#pragma unroll
        for (int j = 0; j < 4; ++j) {
            cp16(base + 8192 + tid * 64 + ((j ^ ((tid >> 1) & 3)) << 4),
                 B + (size_t)(n0 + tid) * ldb + k0 + j * 8);
        }
    };

    const int warp = tid >> 5, lane = tid & 31;
    const int wm = warp >> 2, wn = warp & 3;          // 2m x 4n warp grid
    const int rselA = (lane & 7) + (((lane >> 3) & 1) << 3);
    const int chA   = (lane >> 4) & 1;
    const int rselB = (lane & 7) + (((lane >> 4) & 1) << 3);
    const int chB   = (lane >> 3) & 1;

    float acc[4][8][4];
#pragma unroll
    for (int a = 0; a < 4; ++a)
#pragma unroll
        for (int b = 0; b < 8; ++b)
#pragma unroll
            for (int c = 0; c < 4; ++c) acc[a][b][c] = 0.f;

    auto compute_tile = [&](int buf) {
        const uint32_t abase = S0 + (uint32_t)buf * 24576;
        const uint32_t bbase = abase + 8192;
#pragma unroll
        for (int ks = 0; ks < 2; ++ks) {
            uint32_t aH[4][4];
            const int g = 2 * ks + chA;
#pragma unroll
            for (int mf = 0; mf < 4; ++mf) {
                int row = wm * 64 + mf * 16 + rselA;
                ldsm_x4(aH[mf], abase + row * 64 + ((g ^ ((row >> 1) & 3)) << 4));
            }
            const int gb = 2 * ks + chB;
#pragma unroll
            for (int np = 0; np < 4; ++np) {
                uint32_t bh[4];
                int rowb = wn * 64 + np * 16 + rselB;
                ldsm_x4(bh, bbase + rowb * 64 + ((gb ^ ((rowb >> 1) & 3)) << 4));
#pragma unroll
                for (int mf = 0; mf < 4; ++mf) {
                    mma_f16(acc[mf][2 * np],     aH[mf], bh);
                    mma_f16(acc[mf][2 * np + 1], aH[mf], bh + 2);
                }
            }
        }
    };

    copy_stage(0); cp_commit();
    if (nt > 1) { copy_stage(1); cp_commit(); }
    for (int kt = 0; kt < nt; ++kt) {
        if (kt + 1 < nt) cp_wait<1>(); else cp_wait<0>();
        __syncthreads();
        if (kt + 2 < nt) { copy_stage(kt + 2); cp_commit(); }
        compute_tile(kt % 3);
    }

#pragma unroll
    for (int mf = 0; mf < 4; ++mf) {
        int row = m0 + wm * 64 + mf * 16 + (lane >> 2);
#pragma unroll
        for (int nf = 0; nf < 8; ++nf) {
            int col = n0 + wn * 64 + nf * 8 + (lane & 3) * 2;
            float b0 = bias[col], b1 = bias[col + 1];
            float v0 = acc[mf][nf][0] + b0, v1 = acc[mf][nf][1] + b1;
            float v2 = acc[mf][nf][2] + b0, v3 = acc[mf][nf][3] + b1;
            size_t o0 = (size_t)row * ldc + col;
            size_t o1 = (size_t)(row + 8) * ldc + col;
            if (WF32) {
                *(float2*)(C + o0) = make_float2(v0, v1);
                *(float2*)(C + o1) = make_float2(v2, v3);
            } else {
                *(uint32_t*)(Ch + o0) = packh(__float2half_rn(v0), __float2half_rn(v1));
                *(uint32_t*)(Ch + o1) = packh(__float2half_rn(v2), __float2half_rn(v3));
            }
        }
    }
}

// ---------------- fused flash attention (plain fp16; Q in registers) ----------
__global__ __launch_bounds__(256) void flash_attn(
    const __half* __restrict__ qkvh, __half* __restrict__ outh)
{
    const int qi = 15 - (int)blockIdx.x;
    const int bh = blockIdx.y;
    const int b = bh >> 4, h = bh & 15;
    const int q0 = qi * 128;
    const size_t base = (size_t)b * SEQ * 6144 + (size_t)h * 128;
    const __half* Qp = qkvh + base;
    const __half* Kp = qkvh + base + 2048;
    const __half* Vp = qkvh + base + 4096;

    extern __shared__ char smem[];
    const uint32_t S0 = smem_u32(smem);
    const int tid = threadIdx.x, lane = tid & 31, warp = tid >> 5;

    // Q: 2 p-planes x 128 rows x 128B = 32KB at S0
#pragma unroll
    for (int i = 0; i < 8; ++i) {
        int idx = tid + i * 256;
        int row = idx >> 4, c = idx & 15, p = c >> 3, c8 = c & 7;
        cp16(S0 + p * 16384 + row * 128 + ((c8 ^ (row & 7)) << 4),
             Qp + (size_t)(q0 + row) * 6144 + p * 64 + c8 * 8);
    }
    cp_commit();   // group: Q

    auto copy_kv = [&](int t) {
        const uint32_t sb = S0 + 32768 + (uint32_t)(t & 1) * 32768;
        const int kv0 = t * 64;
#pragma unroll
        for (int q = 0; q < 2; ++q) {
            const __half* src = q ? Vp : Kp;
#pragma unroll
            for (int i = 0; i < 4; ++i) {
                int idx = tid + i * 256;
                int row = idx >> 4, c = idx & 15, p = c >> 3, c8 = c & 7;
                cp16(sb + q * 16384 + p * 8192 + row * 128 + ((c8 ^ (row & 7)) << 4),
                     src + (size_t)(kv0 + row) * 6144 + p * 64 + c8 * 8);
            }
        }
    };

    const int rselA = (lane & 7) + (((lane >> 3) & 1) << 3);
    const int chA   = (lane >> 4) & 1;
    const int rselB = (lane & 7) + (((lane >> 4) & 1) << 3);
    const int chB   = (lane >> 3) & 1;
    const int qr = warp * 16;

    const int nt = 2 * qi + 2;
    copy_kv(0); cp_commit();
    if (nt > 1) { copy_kv(1); cp_commit(); }

    // Q fragments -> registers (loop-invariant)
    cp_wait<2>();            // Q group retired
    __syncthreads();
    uint32_t qf[8][4];
#pragma unroll
    for (int ks = 0; ks < 8; ++ks) {
        int row = qr + rselA;
        int g = ks * 2 + chA, p = g >> 3, c8 = g & 7;
        ldsm_x4(qf[ks], S0 + (uint32_t)p * 16384 + row * 128 + ((c8 ^ (row & 7)) << 4));
    }

    float m0 = -1e30f, m1 = -1e30f, l0 = 0.f, l1 = 0.f;
    float accO[16][4];
#pragma unroll
    for (int j = 0; j < 16; ++j)
#pragma unroll
        for (int c = 0; c < 4; ++c) accO[j][c] = 0.f;

    for (int t = 0; t < nt; ++t) {
        if (t + 1 < nt) cp_wait<1>(); else cp_wait<0>();
        __syncthreads();

        const uint32_t sb = S0 + 32768 + (uint32_t)(t & 1) * 32768;
        const uint32_t sK = sb, sV = sb + 16384;

        float accS[8][4];
#pragma unroll
        for (int j = 0; j < 8; ++j)
#pragma unroll
            for (int c = 0; c < 4; ++c) accS[j][c] = 0.f;

#pragma unroll
        for (int ks = 0; ks < 8; ++ks) {
#pragma unroll
            for (int n2 = 0; n2 < 4; ++n2) {
                uint32_t bH[4];
                int row = n2 * 16 + rselB;
                int g = ks * 2 + chB, p = g >> 3, c8 = g & 7;
                ldsm_x4(bH, sK + (uint32_t)p * 8192 + row * 128 + ((c8 ^ (row & 7)) << 4));
                mma_f16(accS[2 * n2],     qf[ks], bH);
                mma_f16(accS[2 * n2 + 1], qf[ks], bH + 2);
            }
        }

        const float isd = 0.08838834764831845f;
        const int kv0 = t * 64;
        const int grow0 = q0 + qr + (lane >> 2);
        const int grow1 = grow0 + 8;
        const bool masked = (t >= 2 * qi);
#pragma unroll
        for (int nf = 0; nf < 8; ++nf) {
#pragma unroll
            for (int c = 0; c < 4; ++c) accS[nf][c] *= isd;
            if (masked) {
                int col = kv0 + nf * 8 + (lane & 3) * 2;
                if (col     > grow0) accS[nf][0] = -1e30f;
                if (col + 1 > grow0) accS[nf][1] = -1e30f;
                if (col     > grow1) accS[nf][2] = -1e30f;
                if (col + 1 > grow1) accS[nf][3] = -1e30f;
            }
        }
        float mx0 = -1e30f, mx1 = -1e30f;
#pragma unroll
        for (int nf = 0; nf < 8; ++nf) {
            mx0 = fmaxf(mx0, fmaxf(accS[nf][0], accS[nf][1]));
            mx1 = fmaxf(mx1, fmaxf(accS[nf][2], accS[nf][3]));
        }
        mx0 = fmaxf(mx0, __shfl_xor_sync(0xffffffffu, mx0, 1));
        mx0 = fmaxf(mx0, __shfl_xor_sync(0xffffffffu, mx0, 2));
        mx1 = fmaxf(mx1, __shfl_xor_sync(0xffffffffu, mx1, 1));
        mx1 = fmaxf(mx1, __shfl_xor_sync(0xffffffffu, mx1, 2));
        const float nm0 = fmaxf(m0, mx0), nm1 = fmaxf(m1, mx1);
        const float cr0 = __expf(m0 - nm0), cr1 = __expf(m1 - nm1);
        m0 = nm0; m1 = nm1;

        float rs0 = 0.f, rs1 = 0.f;
        uint32_t phr[8], phr8[8];
#pragma unroll
        for (int nf = 0; nf < 8; ++nf) {
            float p0 = __expf(accS[nf][0] - nm0), p1 = __expf(accS[nf][1] - nm0);
            float p2 = __expf(accS[nf][2] - nm1), p3 = __expf(accS[nf][3] - nm1);
            rs0 += p0 + p1; rs1 += p2 + p3;
            phr[nf]  = packh(__float2half_rn(p0), __float2half_rn(p1));
            phr8[nf] = packh(__float2half_rn(p2), __float2half_rn(p3));
        }
        rs0 += __shfl_xor_sync(0xffffffffu, rs0, 1);
        rs0 += __shfl_xor_sync(0xffffffffu, rs0, 2);
        rs1 += __shfl_xor_sync(0xffffffffu, rs1, 1);
        rs1 += __shfl_xor_sync(0xffffffffu, rs1, 2);
        l0 = l0 * cr0 + rs0;
        l1 = l1 * cr1 + rs1;
#pragma unroll
        for (int j = 0; j < 16; ++j) {
            accO[j][0] *= cr0; accO[j][1] *= cr0;
            accO[j][2] *= cr1; accO[j][3] *= cr1;
        }

        // O += P V
#pragma unroll
        for (int ks = 0; ks < 4; ++ks) {
            uint32_t Aph[4] = {phr[2 * ks], phr8[2 * ks], phr[2 * ks + 1], phr8[2 * ks + 1]};
            const int rowv = ks * 16 + (lane & 15);
#pragma unroll
            for (int jj = 0; jj < 4; ++jj) {
                uint32_t vh0[4], vh1[4];
                {
                    int cv = 4 * jj + (lane >> 4), p = cv >> 3, c8 = cv & 7;
                    ldsm_x4_t(vh0, sV + (uint32_t)p * 8192 + rowv * 128 + ((c8 ^ (rowv & 7)) << 4));
                }
                {
                    int cv = 4 * jj + 2 + (lane >> 4), p = cv >> 3, c8 = cv & 7;
                    ldsm_x4_t(vh1, sV + (uint32_t)p * 8192 + rowv * 128 + ((c8 ^ (rowv & 7)) << 4));
                }
                mma_f16(accO[4 * jj],     Aph, vh0);
                mma_f16(accO[4 * jj + 1], Aph, vh0 + 2);
                mma_f16(accO[4 * jj + 2], Aph, vh1);
                mma_f16(accO[4 * jj + 3], Aph, vh1 + 2);
            }
        }

        __syncthreads();
        if (t + 2 < nt) { copy_kv(t + 2); cp_commit(); }
    }

    const float i0 = 1.f / l0, i1 = 1.f / l1;
    const size_t obase = (size_t)b * SEQ * N_EMBD + (size_t)h * 128;
    const int row0 = q0 + qr + (lane >> 2);
#pragma unroll
    for (int j = 0; j < 16; ++j) {
        int d = j * 8 + (lane & 3) * 2;
        size_t o0 = obase + (size_t)row0 * N_EMBD + d;
        size_t o1 = obase + (size_t)(row0 + 8) * N_EMBD + d;
        *(uint32_t*)(outh + o0) = packh(__float2half_rn(accO[j][0] * i0),
                                        __float2half_rn(accO[j][1] * i0));
        *(uint32_t*)(outh + o1) = packh(__float2half_rn(accO[j][2] * i1),
                                        __float2half_rn(accO[j][3] * i1));
    }
}

// ---------------- converts ----------------------------------------------------
__global__ __launch_bounds__(256) void convert_plain(
    const float* __restrict__ in, __half* __restrict__ oh, int n)
{
    for (int i = blockIdx.x * 256 + threadIdx.x; i < n; i += gridDim.x * 256)
        oh[i] = __float2half_rn(in[i]);
}
__global__ __launch_bounds__(256) void transpose_w(
    const float* __restrict__ in, __half* __restrict__ out, int ld_in, int ld_out)
{
    __shared__ float t[32][33];
    const int c0 = blockIdx.x * 32, r0 = blockIdx.y * 32;
    const int tx = threadIdx.x, ty = threadIdx.y;
#pragma unroll
    for (int j = 0; j < 32; j += 8)
        t[ty + j][tx] = in[(size_t)(r0 + ty + j) * ld_in + c0 + tx];
    __syncthreads();
#pragma unroll
    for (int j = 0; j < 32; j += 8)
        out[(size_t)(c0 + ty + j) * ld_out + r0 + tx] = __float2half_rn(t[tx][ty + j]);
}

// ---------------- launch ------------------------------------------------------
extern "C" void kernel_launch(void* const* d_in, const int* in_sizes, int n_in,
                              void* d_out, int out_size)
{
    const float* x     = (const float*)d_in[0];
    const float* Wqkv  = (const float*)d_in[1];
    const float* bqkv  = (const float*)d_in[2];
    const float* Wproj = (const float*)d_in[3];
    const float* bproj = (const float*)d_in[4];
    float* out = (float*)d_out;

    __half *x_h, *wq, *wp, *qkv_h, *at_h;
    cudaGetSymbolAddress((void**)&x_h, g_x_h);
    cudaGetSymbolAddress((void**)&wq, g_wqkvT);
    cudaGetSymbolAddress((void**)&wp, g_wprojT);
    cudaGetSymbolAddress((void**)&qkv_h, g_qkv_h);
    cudaGetSymbolAddress((void**)&at_h, g_attn_h);

    const int GEMM_SMEM  = 73728;    // 3 stages x 24KB (A 8KB + B 16KB)
    const int FLASH_SMEM = 98304;    // Q 32KB + 2 stages x 32KB
    cudaFuncSetAttribute(gemm_big<false>,
                         cudaFuncAttributeMaxDynamicSharedMemorySize, GEMM_SMEM);
    cudaFuncSetAttribute(gemm_big<true>,
                         cudaFuncAttributeMaxDynamicSharedMemorySize, GEMM_SMEM);
    cudaFuncSetAttribute(flash_attn,
                         cudaFuncAttributeMaxDynamicSharedMemorySize, FLASH_SMEM);

    const int M = BATCH * SEQ, E = N_EMBD, E3 = 3 * N_EMBD;

    convert_plain<<<4096, 256>>>(x, x_h, M * E);
    transpose_w<<<dim3(E3 / 32, E / 32), dim3(32, 8)>>>(Wqkv, wq, E3, E);
    transpose_w<<<dim3(E / 32, E / 32), dim3(32, 8)>>>(Wproj, wp, E, E);

    // 1) qkv = x @ Wqkv + b  (64x64 warp tiles)
    gemm_big<false><<<dim3(E3 / 256, M / 128), 256, GEMM_SMEM>>>(
        x_h, wq, bqkv, nullptr, qkv_h, E, E, E, E3);

    // 2-4) fused flash attention (Q in registers)
    flash_attn<<<dim3(SEQ / 128, BATCH * N_HEAD), 256, FLASH_SMEM>>>(qkv_h, at_h);

    // 5) out = attn @ Wproj + b  (64x64 warp tiles, fp32 out)
    gemm_big<true><<<dim3(E / 256, M / 128), 256, GEMM_SMEM>>>(
        at_h, wp, bproj, out, nullptr, E, E, E, E);
}

// round 14
// speedup vs baseline: 1.3006x; 1.3006x over previous
#include <cuda_runtime.h>
#include <cuda_fp16.h>
#include <cstdint>

#define N_EMBD 2048
#define N_HEAD 16
#define HEAD_DIM 128
#define BATCH 2
#define SEQ 2048

#define BM 128
#define BN 128

// ---------------- scratch ----------------------------------------------------
__device__ __half g_x_h[(size_t)BATCH * SEQ * N_EMBD];
__device__ __half g_wqkvT[(size_t)3 * N_EMBD * N_EMBD];
__device__ __half g_wprojT[(size_t)N_EMBD * N_EMBD];
__device__ __half g_qkv_h[(size_t)BATCH * SEQ * 3 * N_EMBD];
__device__ __half g_attn_h[(size_t)BATCH * SEQ * N_EMBD];

// ---------------- PTX helpers -------------------------------------------------
__device__ __forceinline__ uint32_t smem_u32(const void* p) {
    return (uint32_t)__cvta_generic_to_shared(p);
}
__device__ __forceinline__ void ldsm_x4(uint32_t* r, uint32_t addr) {
    asm volatile("ldmatrix.sync.aligned.m8n8.x4.shared.b16 {%0,%1,%2,%3}, [%4];"
                 : "=r"(r[0]), "=r"(r[1]), "=r"(r[2]), "=r"(r[3]) : "r"(addr));
}
__device__ __forceinline__ void ldsm_x4_t(uint32_t* r, uint32_t addr) {
    asm volatile("ldmatrix.sync.aligned.m8n8.x4.trans.shared.b16 {%0,%1,%2,%3}, [%4];"
                 : "=r"(r[0]), "=r"(r[1]), "=r"(r[2]), "=r"(r[3]) : "r"(addr));
}
__device__ __forceinline__ void mma_f16(float* d, const uint32_t* a, const uint32_t* b) {
    asm volatile(
        "mma.sync.aligned.m16n8k16.row.col.f32.f16.f16.f32 "
        "{%0,%1,%2,%3},{%4,%5,%6,%7},{%8,%9},{%0,%1,%2,%3};"
        : "+f"(d[0]), "+f"(d[1]), "+f"(d[2]), "+f"(d[3])
        : "r"(a[0]), "r"(a[1]), "r"(a[2]), "r"(a[3]), "r"(b[0]), "r"(b[1]));
}
__device__ __forceinline__ void cp16(uint32_t dst, const void* src) {
    asm volatile("cp.async.cg.shared.global [%0], [%1], 16;" :: "r"(dst), "l"(src));
}
__device__ __forceinline__ void cp_commit() {
    asm volatile("cp.async.commit_group;" ::: "memory");
}
template <int W> __device__ __forceinline__ void cp_wait() {
    asm volatile("cp.async.wait_group %0;" :: "n"(W) : "memory");
}
__device__ __forceinline__ uint32_t packh(__half a, __half b) {
    __half2 t; t.x = a; t.y = b;
    uint32_t u; *(__half2*)&u = t; return u;
}

// ---------------- plain fp16 GEMM, BK=32, 3-stage, 1 sync/tile, 2 CTAs/SM -----
// (proven round-12 config: CTA 128x128, warp tile 32x64)
template <bool WF32>
__global__ __launch_bounds__(256, 2) void gemm_plain32(
    const __half* __restrict__ A, const __half* __restrict__ B,
    const float* __restrict__ bias,
    float* __restrict__ C, __half* __restrict__ Ch,
    int K, int lda, int ldb, int ldc)
{
    extern __shared__ char smem[];
    const int tid = threadIdx.x;
    const int m0 = blockIdx.y * BM, n0 = blockIdx.x * BN;
    const int nt = K >> 5;

    const uint32_t S0 = smem_u32(smem);
    const int rb  = tid >> 1;
    const int cb0 = (tid & 1) * 2;

    auto copy_stage = [&](int kt) {
        const uint32_t base = S0 + (uint32_t)(kt % 3) * 16384;
        const int k0 = kt << 5;
#pragma unroll
        for (int j = 0; j < 2; ++j) {
            int c = cb0 + j;
            uint32_t sw = rb * 64 + ((c ^ ((rb >> 1) & 3)) << 4);
            cp16(base + sw,        A + (size_t)(m0 + rb) * lda + k0 + c * 8);
            cp16(base + 8192 + sw, B + (size_t)(n0 + rb) * ldb + k0 + c * 8);
        }
    };

    const int warp = tid >> 5, lane = tid & 31;
    const int wm = warp >> 1, wn = warp & 1;
    const int rselA = (lane & 7) + (((lane >> 3) & 1) << 3);
    const int chA   = (lane >> 4) & 1;
    const int rselB = (lane & 7) + (((lane >> 4) & 1) << 3);
    const int chB   = (lane >> 3) & 1;

    float acc[2][8][4];
#pragma unroll
    for (int a = 0; a < 2; ++a)
#pragma unroll
        for (int b = 0; b < 8; ++b)
#pragma unroll
            for (int c = 0; c < 4; ++c) acc[a][b][c] = 0.f;

    auto compute_tile = [&](int buf) {
        const uint32_t abase = S0 + (uint32_t)buf * 16384;
        const uint32_t bbase = abase + 8192;
#pragma unroll
        for (int ks = 0; ks < 2; ++ks) {
            uint32_t aH[2][4];
            const int g = 2 * ks + chA;
#pragma unroll
            for (int mf = 0; mf < 2; ++mf) {
                int row = wm * 32 + mf * 16 + rselA;
                ldsm_x4(aH[mf], abase + row * 64 + ((g ^ ((row >> 1) & 3)) << 4));
            }
            const int gb = 2 * ks + chB;
#pragma unroll
            for (int np = 0; np < 4; ++np) {
                uint32_t bh[4];
                int rowb = wn * 64 + np * 16 + rselB;
                ldsm_x4(bh, bbase + rowb * 64 + ((gb ^ ((rowb >> 1) & 3)) << 4));
#pragma unroll
                for (int mf = 0; mf < 2; ++mf) {
                    mma_f16(acc[mf][2 * np],     aH[mf], bh);
                    mma_f16(acc[mf][2 * np + 1], aH[mf], bh + 2);
                }
            }
        }
    };

    copy_stage(0); cp_commit();
    if (nt > 1) { copy_stage(1); cp_commit(); }
    for (int kt = 0; kt < nt; ++kt) {
        if (kt + 1 < nt) cp_wait<1>(); else cp_wait<0>();
        __syncthreads();
        if (kt + 2 < nt) { copy_stage(kt + 2); cp_commit(); }
        compute_tile(kt % 3);
    }

#pragma unroll
    for (int mf = 0; mf < 2; ++mf) {
        int row = m0 + wm * 32 + mf * 16 + (lane >> 2);
#pragma unroll
        for (int nf = 0; nf < 8; ++nf) {
            int col = n0 + wn * 64 + nf * 8 + (lane & 3) * 2;
            float b0 = bias[col], b1 = bias[col + 1];
            float v0 = acc[mf][nf][0] + b0, v1 = acc[mf][nf][1] + b1;
            float v2 = acc[mf][nf][2] + b0, v3 = acc[mf][nf][3] + b1;
            size_t o0 = (size_t)row * ldc + col;
            size_t o1 = (size_t)(row + 8) * ldc + col;
            if (WF32) {
                *(float2*)(C + o0) = make_float2(v0, v1);
                *(float2*)(C + o1) = make_float2(v2, v3);
            } else {
                *(uint32_t*)(Ch + o0) = packh(__float2half_rn(v0), __float2half_rn(v1));
                *(uint32_t*)(Ch + o1) = packh(__float2half_rn(v2), __float2half_rn(v3));
            }
        }
    }
}

// ---------------- fused flash attention (plain fp16; Q in registers) ----------
__global__ __launch_bounds__(256) void flash_attn(
    const __half* __restrict__ qkvh, __half* __restrict__ outh)
{
    const int qi = 15 - (int)blockIdx.x;
    const int bh = blockIdx.y;
    const int b = bh >> 4, h = bh & 15;
    const int q0 = qi * 128;
    const size_t base = (size_t)b * SEQ * 6144 + (size_t)h * 128;
    const __half* Qp = qkvh + base;
    const __half* Kp = qkvh + base + 2048;
    const __half* Vp = qkvh + base + 4096;

    extern __shared__ char smem[];
    const uint32_t S0 = smem_u32(smem);
    const int tid = threadIdx.x, lane = tid & 31, warp = tid >> 5;

    // Q: 2 p-planes x 128 rows x 128B = 32KB at S0
#pragma unroll
    for (int i = 0; i < 8; ++i) {
        int idx = tid + i * 256;
        int row = idx >> 4, c = idx & 15, p = c >> 3, c8 = c & 7;
        cp16(S0 + p * 16384 + row * 128 + ((c8 ^ (row & 7)) << 4),
             Qp + (size_t)(q0 + row) * 6144 + p * 64 + c8 * 8);
    }
    cp_commit();   // group: Q

    auto copy_kv = [&](int t) {
        const uint32_t sb = S0 + 32768 + (uint32_t)(t & 1) * 32768;
        const int kv0 = t * 64;
#pragma unroll
        for (int q = 0; q < 2; ++q) {
            const __half* src = q ? Vp : Kp;
#pragma unroll
            for (int i = 0; i < 4; ++i) {
                int idx = tid + i * 256;
                int row = idx >> 4, c = idx & 15, p = c >> 3, c8 = c & 7;
                cp16(sb + q * 16384 + p * 8192 + row * 128 + ((c8 ^ (row & 7)) << 4),
                     src + (size_t)(kv0 + row) * 6144 + p * 64 + c8 * 8);
            }
        }
    };

    const int rselA = (lane & 7) + (((lane >> 3) & 1) << 3);
    const int chA   = (lane >> 4) & 1;
    const int rselB = (lane & 7) + (((lane >> 4) & 1) << 3);
    const int chB   = (lane >> 3) & 1;
    const int qr = warp * 16;

    const int nt = 2 * qi + 2;
    copy_kv(0); cp_commit();
    if (nt > 1) { copy_kv(1); cp_commit(); }

    // Q fragments -> registers (loop-invariant)
    cp_wait<2>();            // Q group retired (2 KV groups may be pending)
    __syncthreads();
    uint32_t qf[8][4];
#pragma unroll
    for (int ks = 0; ks < 8; ++ks) {
        int row = qr + rselA;
        int g = ks * 2 + chA, p = g >> 3, c8 = g & 7;
        ldsm_x4(qf[ks], S0 + (uint32_t)p * 16384 + row * 128 + ((c8 ^ (row & 7)) << 4));
    }

    float m0 = -1e30f, m1 = -1e30f, l0 = 0.f, l1 = 0.f;
    float accO[16][4];
#pragma unroll
    for (int j = 0; j < 16; ++j)
#pragma unroll
        for (int c = 0; c < 4; ++c) accO[j][c] = 0.f;

    for (int t = 0; t < nt; ++t) {
        if (t + 1 < nt) cp_wait<1>(); else cp_wait<0>();
        __syncthreads();

        const uint32_t sb = S0 + 32768 + (uint32_t)(t & 1) * 32768;
        const uint32_t sK = sb, sV = sb + 16384;

        float accS[8][4];
#pragma unroll
        for (int j = 0; j < 8; ++j)
#pragma unroll
            for (int c = 0; c < 4; ++c) accS[j][c] = 0.f;

#pragma unroll
        for (int ks = 0; ks < 8; ++ks) {
#pragma unroll
            for (int n2 = 0; n2 < 4; ++n2) {
                uint32_t bH[4];
                int row = n2 * 16 + rselB;
                int g = ks * 2 + chB, p = g >> 3, c8 = g & 7;
                ldsm_x4(bH, sK + (uint32_t)p * 8192 + row * 128 + ((c8 ^ (row & 7)) << 4));
                mma_f16(accS[2 * n2],     qf[ks], bH);
                mma_f16(accS[2 * n2 + 1], qf[ks], bH + 2);
            }
        }

        const float isd = 0.08838834764831845f;
        const int kv0 = t * 64;
        const int grow0 = q0 + qr + (lane >> 2);
        const int grow1 = grow0 + 8;
        const bool masked = (t >= 2 * qi);
#pragma unroll
        for (int nf = 0; nf < 8; ++nf) {
#pragma unroll
            for (int c = 0; c < 4; ++c) accS[nf][c] *= isd;
            if (masked) {
                int col = kv0 + nf * 8 + (lane & 3) * 2;
                if (col     > grow0) accS[nf][0] = -1e30f;
                if (col + 1 > grow0) accS[nf][1] = -1e30f;
                if (col     > grow1) accS[nf][2] = -1e30f;
                if (col + 1 > grow1) accS[nf][3] = -1e30f;
            }
        }
        float mx0 = -1e30f, mx1 = -1e30f;
#pragma unroll
        for (int nf = 0; nf < 8; ++nf) {
            mx0 = fmaxf(mx0, fmaxf(accS[nf][0], accS[nf][1]));
            mx1 = fmaxf(mx1, fmaxf(accS[nf][2], accS[nf][3]));
        }
        mx0 = fmaxf(mx0, __shfl_xor_sync(0xffffffffu, mx0, 1));
        mx0 = fmaxf(mx0, __shfl_xor_sync(0xffffffffu, mx0, 2));
        mx1 = fmaxf(mx1, __shfl_xor_sync(0xffffffffu, mx1, 1));
        mx1 = fmaxf(mx1, __shfl_xor_sync(0xffffffffu, mx1, 2));
        const float nm0 = fmaxf(m0, mx0), nm1 = fmaxf(m1, mx1);
        const float cr0 = __expf(m0 - nm0), cr1 = __expf(m1 - nm1);
        m0 = nm0; m1 = nm1;

        float rs0 = 0.f, rs1 = 0.f;
        uint32_t phr[8], phr8[8];
#pragma unroll
        for (int nf = 0; nf < 8; ++nf) {
            float p0 = __expf(accS[nf][0] - nm0), p1 = __expf(accS[nf][1] - nm0);
            float p2 = __expf(accS[nf][2] - nm1), p3 = __expf(accS[nf][3] - nm1);
            rs0 += p0 + p1; rs1 += p2 + p3;
            phr[nf]  = packh(__float2half_rn(p0), __float2half_rn(p1));
            phr8[nf] = packh(__float2half_rn(p2), __float2half_rn(p3));
        }
        rs0 += __shfl_xor_sync(0xffffffffu, rs0, 1);
        rs0 += __shfl_xor_sync(0xffffffffu, rs0, 2);
        rs1 += __shfl_xor_sync(0xffffffffu, rs1, 1);
        rs1 += __shfl_xor_sync(0xffffffffu, rs1, 2);
        l0 = l0 * cr0 + rs0;
        l1 = l1 * cr1 + rs1;
#pragma unroll
        for (int j = 0; j < 16; ++j) {
            accO[j][0] *= cr0; accO[j][1] *= cr0;
            accO[j][2] *= cr1; accO[j][3] *= cr1;
        }

        // O += P V
#pragma unroll
        for (int ks = 0; ks < 4; ++ks) {
            uint32_t Aph[4] = {phr[2 * ks], phr8[2 * ks], phr[2 * ks + 1], phr8[2 * ks + 1]};
            const int rowv = ks * 16 + (lane & 15);
#pragma unroll
            for (int jj = 0; jj < 4; ++jj) {
                uint32_t vh0[4], vh1[4];
                {
                    int cv = 4 * jj + (lane >> 4), p = cv >> 3, c8 = cv & 7;
                    ldsm_x4_t(vh0, sV + (uint32_t)p * 8192 + rowv * 128 + ((c8 ^ (rowv & 7)) << 4));
                }
                {
                    int cv = 4 * jj + 2 + (lane >> 4), p = cv >> 3, c8 = cv & 7;
                    ldsm_x4_t(vh1, sV + (uint32_t)p * 8192 + rowv * 128 + ((c8 ^ (rowv & 7)) << 4));
                }
                mma_f16(accO[4 * jj],     Aph, vh0);
                mma_f16(accO[4 * jj + 1], Aph, vh0 + 2);
                mma_f16(accO[4 * jj + 2], Aph, vh1);
                mma_f16(accO[4 * jj + 3], Aph, vh1 + 2);
            }
        }

        __syncthreads();
        if (t + 2 < nt) { copy_kv(t + 2); cp_commit(); }
    }

    const float i0 = 1.f / l0, i1 = 1.f / l1;
    const size_t obase = (size_t)b * SEQ * N_EMBD + (size_t)h * 128;
    const int row0 = q0 + qr + (lane >> 2);
#pragma unroll
    for (int j = 0; j < 16; ++j) {
        int d = j * 8 + (lane & 3) * 2;
        size_t o0 = obase + (size_t)row0 * N_EMBD + d;
        size_t o1 = obase + (size_t)(row0 + 8) * N_EMBD + d;
        *(uint32_t*)(outh + o0) = packh(__float2half_rn(accO[j][0] * i0),
                                        __float2half_rn(accO[j][1] * i0));
        *(uint32_t*)(outh + o1) = packh(__float2half_rn(accO[j][2] * i1),
                                        __float2half_rn(accO[j][3] * i1));
    }
}

// ---------------- converts ----------------------------------------------------
__global__ __launch_bounds__(256) void convert_plain(
    const float* __restrict__ in, __half* __restrict__ oh, int n)
{
    for (int i = blockIdx.x * 256 + threadIdx.x; i < n; i += gridDim.x * 256)
        oh[i] = __float2half_rn(in[i]);
}
__global__ __launch_bounds__(256) void transpose_w(
    const float* __restrict__ in, __half* __restrict__ out, int ld_in, int ld_out)
{
    __shared__ float t[32][33];
    const int c0 = blockIdx.x * 32, r0 = blockIdx.y * 32;
    const int tx = threadIdx.x, ty = threadIdx.y;
#pragma unroll
    for (int j = 0; j < 32; j += 8)
        t[ty + j][tx] = in[(size_t)(r0 + ty + j) * ld_in + c0 + tx];
    __syncthreads();
#pragma unroll
    for (int j = 0; j < 32; j += 8)
        out[(size_t)(c0 + ty + j) * ld_out + r0 + tx] = __float2half_rn(t[tx][ty + j]);
}

// ---------------- launch ------------------------------------------------------
extern "C" void kernel_launch(void* const* d_in, const int* in_sizes, int n_in,
                              void* d_out, int out_size)
{
    const float* x     = (const float*)d_in[0];
    const float* Wqkv  = (const float*)d_in[1];
    const float* bqkv  = (const float*)d_in[2];
    const float* Wproj = (const float*)d_in[3];
    const float* bproj = (const float*)d_in[4];
    float* out = (float*)d_out;

    __half *x_h, *wq, *wp, *qkv_h, *at_h;
    cudaGetSymbolAddress((void**)&x_h, g_x_h);
    cudaGetSymbolAddress((void**)&wq, g_wqkvT);
    cudaGetSymbolAddress((void**)&wp, g_wprojT);
    cudaGetSymbolAddress((void**)&qkv_h, g_qkv_h);
    cudaGetSymbolAddress((void**)&at_h, g_attn_h);

    const int GEMM_SMEM  = 49152;    // 3 stages x 16KB
    const int FLASH_SMEM = 98304;    // Q 32KB + 2 stages x 32KB
    cudaFuncSetAttribute(gemm_plain32<false>,
                         cudaFuncAttributeMaxDynamicSharedMemorySize, GEMM_SMEM);
    cudaFuncSetAttribute(gemm_plain32<true>,
                         cudaFuncAttributeMaxDynamicSharedMemorySize, GEMM_SMEM);
    cudaFuncSetAttribute(flash_attn,
                         cudaFuncAttributeMaxDynamicSharedMemorySize, FLASH_SMEM);

    const int M = BATCH * SEQ, E = N_EMBD, E3 = 3 * N_EMBD;

    convert_plain<<<4096, 256>>>(x, x_h, M * E);
    transpose_w<<<dim3(E3 / 32, E / 32), dim3(32, 8)>>>(Wqkv, wq, E3, E);
    transpose_w<<<dim3(E / 32, E / 32), dim3(32, 8)>>>(Wproj, wp, E, E);

    // 1) qkv = x @ Wqkv + b  (round-12 proven GEMM)
    gemm_plain32<false><<<dim3(E3 / BN, M / BM), 256, GEMM_SMEM>>>(
        x_h, wq, bqkv, nullptr, qkv_h, E, E, E, E3);

    // 2-4) fused flash attention (Q in registers)
    flash_attn<<<dim3(SEQ / 128, BATCH * N_HEAD), 256, FLASH_SMEM>>>(qkv_h, at_h);

    // 5) out = attn @ Wproj + b
    gemm_plain32<true><<<dim3(E / BN, M / BM), 256, GEMM_SMEM>>>(
        at_h, wp, bproj, out, nullptr, E, E, E, E);
}

// round 15
// speedup vs baseline: 1.3494x; 1.0375x over previous
#include <cuda_runtime.h>
#include <cuda_fp16.h>
#include <cstdint>

#define N_EMBD 2048
#define N_HEAD 16
#define HEAD_DIM 128
#define BATCH 2
#define SEQ 2048

#define BM 128
#define BN 128

// ---------------- scratch ----------------------------------------------------
__device__ __half g_x_h[(size_t)BATCH * SEQ * N_EMBD];
__device__ __half g_wqkvT[(size_t)3 * N_EMBD * N_EMBD];
__device__ __half g_wprojT[(size_t)N_EMBD * N_EMBD];
__device__ __half g_qkv_h[(size_t)BATCH * SEQ * 3 * N_EMBD];
__device__ __half g_attn_h[(size_t)BATCH * SEQ * N_EMBD];

// ---------------- PTX helpers -------------------------------------------------
__device__ __forceinline__ uint32_t smem_u32(const void* p) {
    return (uint32_t)__cvta_generic_to_shared(p);
}
__device__ __forceinline__ void ldsm_x4(uint32_t* r, uint32_t addr) {
    asm volatile("ldmatrix.sync.aligned.m8n8.x4.shared.b16 {%0,%1,%2,%3}, [%4];"
                 : "=r"(r[0]), "=r"(r[1]), "=r"(r[2]), "=r"(r[3]) : "r"(addr));
}
__device__ __forceinline__ void ldsm_x4_t(uint32_t* r, uint32_t addr) {
    asm volatile("ldmatrix.sync.aligned.m8n8.x4.trans.shared.b16 {%0,%1,%2,%3}, [%4];"
                 : "=r"(r[0]), "=r"(r[1]), "=r"(r[2]), "=r"(r[3]) : "r"(addr));
}
__device__ __forceinline__ void mma_f16(float* d, const uint32_t* a, const uint32_t* b) {
    asm volatile(
        "mma.sync.aligned.m16n8k16.row.col.f32.f16.f16.f32 "
        "{%0,%1,%2,%3},{%4,%5,%6,%7},{%8,%9},{%0,%1,%2,%3};"
        : "+f"(d[0]), "+f"(d[1]), "+f"(d[2]), "+f"(d[3])
        : "r"(a[0]), "r"(a[1]), "r"(a[2]), "r"(a[3]), "r"(b[0]), "r"(b[1]));
}
__device__ __forceinline__ void cp16(uint32_t dst, const void* src) {
    asm volatile("cp.async.cg.shared.global [%0], [%1], 16;" :: "r"(dst), "l"(src));
}
__device__ __forceinline__ void cp_commit() {
    asm volatile("cp.async.commit_group;" ::: "memory");
}
template <int W> __device__ __forceinline__ void cp_wait() {
    asm volatile("cp.async.wait_group %0;" :: "n"(W) : "memory");
}
__device__ __forceinline__ uint32_t packh(__half a, __half b) {
    __half2 t; t.x = a; t.y = b;
    uint32_t u; *(__half2*)&u = t; return u;
}

// ---------------- plain fp16 GEMM (round-12 proven; Q-prescale epilogue) ------
template <bool WF32>
__global__ __launch_bounds__(256, 2) void gemm_plain32(
    const __half* __restrict__ A, const __half* __restrict__ B,
    const float* __restrict__ bias,
    float* __restrict__ C, __half* __restrict__ Ch,
    int K, int lda, int ldb, int ldc, int qlim, float qscale)
{
    extern __shared__ char smem[];
    const int tid = threadIdx.x;
    const int m0 = blockIdx.y * BM, n0 = blockIdx.x * BN;
    const int nt = K >> 5;

    const uint32_t S0 = smem_u32(smem);
    const int rb  = tid >> 1;
    const int cb0 = (tid & 1) * 2;

    auto copy_stage = [&](int kt) {
        const uint32_t base = S0 + (uint32_t)(kt % 3) * 16384;
        const int k0 = kt << 5;
#pragma unroll
        for (int j = 0; j < 2; ++j) {
            int c = cb0 + j;
            uint32_t sw = rb * 64 + ((c ^ ((rb >> 1) & 3)) << 4);
            cp16(base + sw,        A + (size_t)(m0 + rb) * lda + k0 + c * 8);
            cp16(base + 8192 + sw, B + (size_t)(n0 + rb) * ldb + k0 + c * 8);
        }
    };

    const int warp = tid >> 5, lane = tid & 31;
    const int wm = warp >> 1, wn = warp & 1;
    const int rselA = (lane & 7) + (((lane >> 3) & 1) << 3);
    const int chA   = (lane >> 4) & 1;
    const int rselB = (lane & 7) + (((lane >> 4) & 1) << 3);
    const int chB   = (lane >> 3) & 1;

    float acc[2][8][4];
#pragma unroll
    for (int a = 0; a < 2; ++a)
#pragma unroll
        for (int b = 0; b < 8; ++b)
#pragma unroll
            for (int c = 0; c < 4; ++c) acc[a][b][c] = 0.f;

    auto compute_tile = [&](int buf) {
        const uint32_t abase = S0 + (uint32_t)buf * 16384;
        const uint32_t bbase = abase + 8192;
#pragma unroll
        for (int ks = 0; ks < 2; ++ks) {
            uint32_t aH[2][4];
            const int g = 2 * ks + chA;
#pragma unroll
            for (int mf = 0; mf < 2; ++mf) {
                int row = wm * 32 + mf * 16 + rselA;
                ldsm_x4(aH[mf], abase + row * 64 + ((g ^ ((row >> 1) & 3)) << 4));
            }
            const int gb = 2 * ks + chB;
#pragma unroll
            for (int np = 0; np < 4; ++np) {
                uint32_t bh[4];
                int rowb = wn * 64 + np * 16 + rselB;
                ldsm_x4(bh, bbase + rowb * 64 + ((gb ^ ((rowb >> 1) & 3)) << 4));
#pragma unroll
                for (int mf = 0; mf < 2; ++mf) {
                    mma_f16(acc[mf][2 * np],     aH[mf], bh);
                    mma_f16(acc[mf][2 * np + 1], aH[mf], bh + 2);
                }
            }
        }
    };

    copy_stage(0); cp_commit();
    if (nt > 1) { copy_stage(1); cp_commit(); }
    for (int kt = 0; kt < nt; ++kt) {
        if (kt + 1 < nt) cp_wait<1>(); else cp_wait<0>();
        __syncthreads();
        if (kt + 2 < nt) { copy_stage(kt + 2); cp_commit(); }
        compute_tile(kt % 3);
    }

#pragma unroll
    for (int mf = 0; mf < 2; ++mf) {
        int row = m0 + wm * 32 + mf * 16 + (lane >> 2);
#pragma unroll
        for (int nf = 0; nf < 8; ++nf) {
            int col = n0 + wn * 64 + nf * 8 + (lane & 3) * 2;
            float b0 = bias[col], b1 = bias[col + 1];
            float sc = (col < qlim) ? qscale : 1.0f;
            float v0 = (acc[mf][nf][0] + b0) * sc, v1 = (acc[mf][nf][1] + b1) * sc;
            float v2 = (acc[mf][nf][2] + b0) * sc, v3 = (acc[mf][nf][3] + b1) * sc;
            size_t o0 = (size_t)row * ldc + col;
            size_t o1 = (size_t)(row + 8) * ldc + col;
            if (WF32) {
                *(float2*)(C + o0) = make_float2(v0, v1);
                *(float2*)(C + o1) = make_float2(v2, v3);
            } else {
                *(uint32_t*)(Ch + o0) = packh(__float2half_rn(v0), __float2half_rn(v1));
                *(uint32_t*)(Ch + o1) = packh(__float2half_rn(v2), __float2half_rn(v3));
            }
        }
    }
}

// ---------------- fused flash attention (Q pre-scaled; exp2 softmax) ----------
__global__ __launch_bounds__(256) void flash_attn(
    const __half* __restrict__ qkvh, __half* __restrict__ outh)
{
    const int qi = 15 - (int)blockIdx.x;
    const int bh = blockIdx.y;
    const int b = bh >> 4, h = bh & 15;
    const int q0 = qi * 128;
    const size_t base = (size_t)b * SEQ * 6144 + (size_t)h * 128;
    const __half* Qp = qkvh + base;
    const __half* Kp = qkvh + base + 2048;
    const __half* Vp = qkvh + base + 4096;

    extern __shared__ char smem[];
    const uint32_t S0 = smem_u32(smem);
    const int tid = threadIdx.x, lane = tid & 31, warp = tid >> 5;

    // Q: 2 p-planes x 128 rows x 128B = 32KB at S0
#pragma unroll
    for (int i = 0; i < 8; ++i) {
        int idx = tid + i * 256;
        int row = idx >> 4, c = idx & 15, p = c >> 3, c8 = c & 7;
        cp16(S0 + p * 16384 + row * 128 + ((c8 ^ (row & 7)) << 4),
             Qp + (size_t)(q0 + row) * 6144 + p * 64 + c8 * 8);
    }
    cp_commit();   // group: Q

    auto copy_kv = [&](int t) {
        const uint32_t sb = S0 + 32768 + (uint32_t)(t & 1) * 32768;
        const int kv0 = t * 64;
#pragma unroll
        for (int q = 0; q < 2; ++q) {
            const __half* src = q ? Vp : Kp;
#pragma unroll
            for (int i = 0; i < 4; ++i) {
                int idx = tid + i * 256;
                int row = idx >> 4, c = idx & 15, p = c >> 3, c8 = c & 7;
                cp16(sb + q * 16384 + p * 8192 + row * 128 + ((c8 ^ (row & 7)) << 4),
                     src + (size_t)(kv0 + row) * 6144 + p * 64 + c8 * 8);
            }
        }
    };

    const int rselA = (lane & 7) + (((lane >> 3) & 1) << 3);
    const int chA   = (lane >> 4) & 1;
    const int rselB = (lane & 7) + (((lane >> 4) & 1) << 3);
    const int chB   = (lane >> 3) & 1;
    const int qr = warp * 16;

    const int nt = 2 * qi + 2;
    copy_kv(0); cp_commit();
    if (nt > 1) { copy_kv(1); cp_commit(); }

    // Q fragments -> registers (loop-invariant)
    cp_wait<2>();
    __syncthreads();
    uint32_t qf[8][4];
#pragma unroll
    for (int ks = 0; ks < 8; ++ks) {
        int row = qr + rselA;
        int g = ks * 2 + chA, p = g >> 3, c8 = g & 7;
        ldsm_x4(qf[ks], S0 + (uint32_t)p * 16384 + row * 128 + ((c8 ^ (row & 7)) << 4));
    }

    float m0 = -1e30f, m1 = -1e30f, l0 = 0.f, l1 = 0.f;
    float accO[16][4];
#pragma unroll
    for (int j = 0; j < 16; ++j)
#pragma unroll
        for (int c = 0; c < 4; ++c) accO[j][c] = 0.f;

    for (int t = 0; t < nt; ++t) {
        if (t + 1 < nt) cp_wait<1>(); else cp_wait<0>();
        __syncthreads();

        const uint32_t sb = S0 + 32768 + (uint32_t)(t & 1) * 32768;
        const uint32_t sK = sb, sV = sb + 16384;

        float accS[8][4];
#pragma unroll
        for (int j = 0; j < 8; ++j)
#pragma unroll
            for (int c = 0; c < 4; ++c) accS[j][c] = 0.f;

        // S = Q K^T : batch the 4 K-fragment LDSMs, then 8 MMAs per ks
#pragma unroll
        for (int ks = 0; ks < 8; ++ks) {
            uint32_t bH[4][4];
            const int g = ks * 2 + chB, p = g >> 3, c8 = g & 7;
#pragma unroll
            for (int n2 = 0; n2 < 4; ++n2) {
                int row = n2 * 16 + rselB;
                ldsm_x4(bH[n2], sK + (uint32_t)p * 8192 + row * 128 + ((c8 ^ (row & 7)) << 4));
            }
#pragma unroll
            for (int n2 = 0; n2 < 4; ++n2) {
                mma_f16(accS[2 * n2],     qf[ks], bH[n2]);
                mma_f16(accS[2 * n2 + 1], qf[ks], bH[n2] + 2);
            }
        }

        // scores are already scaled by isd*log2e (Q prescale) -> exp2 softmax
        const int kv0 = t * 64;
        const int grow0 = q0 + qr + (lane >> 2);
        const int grow1 = grow0 + 8;
        const bool masked = (t >= 2 * qi);
        if (masked) {
#pragma unroll
            for (int nf = 0; nf < 8; ++nf) {
                int col = kv0 + nf * 8 + (lane & 3) * 2;
                if (col     > grow0) accS[nf][0] = -1e30f;
                if (col + 1 > grow0) accS[nf][1] = -1e30f;
                if (col     > grow1) accS[nf][2] = -1e30f;
                if (col + 1 > grow1) accS[nf][3] = -1e30f;
            }
        }
        float mx0 = -1e30f, mx1 = -1e30f;
#pragma unroll
        for (int nf = 0; nf < 8; ++nf) {
            mx0 = fmaxf(mx0, fmaxf(accS[nf][0], accS[nf][1]));
            mx1 = fmaxf(mx1, fmaxf(accS[nf][2], accS[nf][3]));
        }
        mx0 = fmaxf(mx0, __shfl_xor_sync(0xffffffffu, mx0, 1));
        mx0 = fmaxf(mx0, __shfl_xor_sync(0xffffffffu, mx0, 2));
        mx1 = fmaxf(mx1, __shfl_xor_sync(0xffffffffu, mx1, 1));
        mx1 = fmaxf(mx1, __shfl_xor_sync(0xffffffffu, mx1, 2));
        const float nm0 = fmaxf(m0, mx0), nm1 = fmaxf(m1, mx1);
        const float cr0 = exp2f(m0 - nm0), cr1 = exp2f(m1 - nm1);
        m0 = nm0; m1 = nm1;

        float rs0 = 0.f, rs1 = 0.f;
        uint32_t phr[8], phr8[8];
#pragma unroll
        for (int nf = 0; nf < 8; ++nf) {
            float p0 = exp2f(accS[nf][0] - nm0), p1 = exp2f(accS[nf][1] - nm0);
            float p2 = exp2f(accS[nf][2] - nm1), p3 = exp2f(accS[nf][3] - nm1);
            rs0 += p0 + p1; rs1 += p2 + p3;
            phr[nf]  = packh(__float2half_rn(p0), __float2half_rn(p1));
            phr8[nf] = packh(__float2half_rn(p2), __float2half_rn(p3));
        }
        rs0 += __shfl_xor_sync(0xffffffffu, rs0, 1);
        rs0 += __shfl_xor_sync(0xffffffffu, rs0, 2);
        rs1 += __shfl_xor_sync(0xffffffffu, rs1, 1);
        rs1 += __shfl_xor_sync(0xffffffffu, rs1, 2);
        l0 = l0 * cr0 + rs0;
        l1 = l1 * cr1 + rs1;
#pragma unroll
        for (int j = 0; j < 16; ++j) {
            accO[j][0] *= cr0; accO[j][1] *= cr0;
            accO[j][2] *= cr1; accO[j][3] *= cr1;
        }

        // O += P V : batch the 8 V-fragment LDSMs per ks, then 16 MMAs
#pragma unroll
        for (int ks = 0; ks < 4; ++ks) {
            uint32_t Aph[4] = {phr[2 * ks], phr8[2 * ks], phr[2 * ks + 1], phr8[2 * ks + 1]};
            const int rowv = ks * 16 + (lane & 15);
            uint32_t vf[4][2][4];
#pragma unroll
            for (int jj = 0; jj < 4; ++jj) {
                {
                    int cv = 4 * jj + (lane >> 4), p = cv >> 3, c8 = cv & 7;
                    ldsm_x4_t(vf[jj][0], sV + (uint32_t)p * 8192 + rowv * 128 + ((c8 ^ (rowv & 7)) << 4));
                }
                {
                    int cv = 4 * jj + 2 + (lane >> 4), p = cv >> 3, c8 = cv & 7;
                    ldsm_x4_t(vf[jj][1], sV + (uint32_t)p * 8192 + rowv * 128 + ((c8 ^ (rowv & 7)) << 4));
                }
            }
#pragma unroll
            for (int jj = 0; jj < 4; ++jj) {
                mma_f16(accO[4 * jj],     Aph, vf[jj][0]);
                mma_f16(accO[4 * jj + 1], Aph, vf[jj][0] + 2);
                mma_f16(accO[4 * jj + 2], Aph, vf[jj][1]);
                mma_f16(accO[4 * jj + 3], Aph, vf[jj][1] + 2);
            }
        }

        __syncthreads();
        if (t + 2 < nt) { copy_kv(t + 2); cp_commit(); }
    }

    const float i0 = 1.f / l0, i1 = 1.f / l1;
    const size_t obase = (size_t)b * SEQ * N_EMBD + (size_t)h * 128;
    const int row0 = q0 + qr + (lane >> 2);
#pragma unroll
    for (int j = 0; j < 16; ++j) {
        int d = j * 8 + (lane & 3) * 2;
        size_t o0 = obase + (size_t)row0 * N_EMBD + d;
        size_t o1 = obase + (size_t)(row0 + 8) * N_EMBD + d;
        *(uint32_t*)(outh + o0) = packh(__float2half_rn(accO[j][0] * i0),
                                        __float2half_rn(accO[j][1] * i0));
        *(uint32_t*)(outh + o1) = packh(__float2half_rn(accO[j][2] * i1),
                                        __float2half_rn(accO[j][3] * i1));
    }
}

// ---------------- converts ----------------------------------------------------
__global__ __launch_bounds__(256) void convert_plain4(
    const float* __restrict__ in, __half* __restrict__ oh, int n4)
{
    for (int i = blockIdx.x * 256 + threadIdx.x; i < n4; i += gridDim.x * 256) {
        float4 v = ((const float4*)in)[i];
        uint32_t lo = packh(__float2half_rn(v.x), __float2half_rn(v.y));
        uint32_t hi = packh(__float2half_rn(v.z), __float2half_rn(v.w));
        ((uint2*)oh)[i] = make_uint2(lo, hi);
    }
}
__global__ __launch_bounds__(256) void transpose_w(
    const float* __restrict__ in, __half* __restrict__ out, int ld_in, int ld_out)
{
    __shared__ float t[32][33];
    const int c0 = blockIdx.x * 32, r0 = blockIdx.y * 32;
    const int tx = threadIdx.x, ty = threadIdx.y;
#pragma unroll
    for (int j = 0; j < 32; j += 8)
        t[ty + j][tx] = in[(size_t)(r0 + ty + j) * ld_in + c0 + tx];
    __syncthreads();
#pragma unroll
    for (int j = 0; j < 32; j += 8)
        out[(size_t)(c0 + ty + j) * ld_out + r0 + tx] = __float2half_rn(t[tx][ty + j]);
}

// ---------------- launch ------------------------------------------------------
extern "C" void kernel_launch(void* const* d_in, const int* in_sizes, int n_in,
                              void* d_out, int out_size)
{
    const float* x     = (const float*)d_in[0];
    const float* Wqkv  = (const float*)d_in[1];
    const float* bqkv  = (const float*)d_in[2];
    const float* Wproj = (const float*)d_in[3];
    const float* bproj = (const float*)d_in[4];
    float* out = (float*)d_out;

    __half *x_h, *wq, *wp, *qkv_h, *at_h;
    cudaGetSymbolAddress((void**)&x_h, g_x_h);
    cudaGetSymbolAddress((void**)&wq, g_wqkvT);
    cudaGetSymbolAddress((void**)&wp, g_wprojT);
    cudaGetSymbolAddress((void**)&qkv_h, g_qkv_h);
    cudaGetSymbolAddress((void**)&at_h, g_attn_h);

    const int GEMM_SMEM  = 49152;    // 3 stages x 16KB
    const int FLASH_SMEM = 98304;    // Q 32KB + 2 stages x 32KB
    cudaFuncSetAttribute(gemm_plain32<false>,
                         cudaFuncAttributeMaxDynamicSharedMemorySize, GEMM_SMEM);
    cudaFuncSetAttribute(gemm_plain32<true>,
                         cudaFuncAttributeMaxDynamicSharedMemorySize, GEMM_SMEM);
    cudaFuncSetAttribute(flash_attn,
                         cudaFuncAttributeMaxDynamicSharedMemorySize, FLASH_SMEM);

    const int M = BATCH * SEQ, E = N_EMBD, E3 = 3 * N_EMBD;
    // 1/sqrt(128) * log2(e)
    const float qscale = 0.12751743056057344f;

    convert_plain4<<<4096, 256>>>(x, x_h, M * E / 4);
    transpose_w<<<dim3(E3 / 32, E / 32), dim3(32, 8)>>>(Wqkv, wq, E3, E);
    transpose_w<<<dim3(E / 32, E / 32), dim3(32, 8)>>>(Wproj, wp, E, E);

    // 1) qkv = x @ Wqkv + b; Q columns pre-scaled by isd*log2e
    gemm_plain32<false><<<dim3(E3 / BN, M / BM), 256, GEMM_SMEM>>>(
        x_h, wq, bqkv, nullptr, qkv_h, E, E, E, E3, 2048, qscale);

    // 2-4) fused flash attention (exp2 softmax)
    flash_attn<<<dim3(SEQ / 128, BATCH * N_HEAD), 256, FLASH_SMEM>>>(qkv_h, at_h);

    // 5) out = attn @ Wproj + b
    gemm_plain32<true><<<dim3(E / BN, M / BM), 256, GEMM_SMEM>>>(
        at_h, wp, bproj, out, nullptr, E, E, E, E, 0, 1.0f);
}

// round 16
// speedup vs baseline: 1.3581x; 1.0064x over previous
#include <cuda_runtime.h>
#include <cuda_fp16.h>
#include <cstdint>

#define N_EMBD 2048
#define N_HEAD 16
#define HEAD_DIM 128
#define BATCH 2
#define SEQ 2048

#define BM 128
#define BN 128

// ---------------- scratch ----------------------------------------------------
__device__ __half g_x_h[(size_t)BATCH * SEQ * N_EMBD];
__device__ __half g_wqkvT[(size_t)3 * N_EMBD * N_EMBD];
__device__ __half g_wprojT[(size_t)N_EMBD * N_EMBD];
__device__ __half g_qkv_h[(size_t)BATCH * SEQ * 3 * N_EMBD];
__device__ __half g_attn_h[(size_t)BATCH * SEQ * N_EMBD];

// ---------------- PTX helpers -------------------------------------------------
__device__ __forceinline__ uint32_t smem_u32(const void* p) {
    return (uint32_t)__cvta_generic_to_shared(p);
}
__device__ __forceinline__ void ldsm_x4(uint32_t* r, uint32_t addr) {
    asm volatile("ldmatrix.sync.aligned.m8n8.x4.shared.b16 {%0,%1,%2,%3}, [%4];"
                 : "=r"(r[0]), "=r"(r[1]), "=r"(r[2]), "=r"(r[3]) : "r"(addr));
}
__device__ __forceinline__ void ldsm_x4_t(uint32_t* r, uint32_t addr) {
    asm volatile("ldmatrix.sync.aligned.m8n8.x4.trans.shared.b16 {%0,%1,%2,%3}, [%4];"
                 : "=r"(r[0]), "=r"(r[1]), "=r"(r[2]), "=r"(r[3]) : "r"(addr));
}
__device__ __forceinline__ void mma_f16(float* d, const uint32_t* a, const uint32_t* b) {
    asm volatile(
        "mma.sync.aligned.m16n8k16.row.col.f32.f16.f16.f32 "
        "{%0,%1,%2,%3},{%4,%5,%6,%7},{%8,%9},{%0,%1,%2,%3};"
        : "+f"(d[0]), "+f"(d[1]), "+f"(d[2]), "+f"(d[3])
        : "r"(a[0]), "r"(a[1]), "r"(a[2]), "r"(a[3]), "r"(b[0]), "r"(b[1]));
}
__device__ __forceinline__ void cp16(uint32_t dst, const void* src) {
    asm volatile("cp.async.cg.shared.global [%0], [%1], 16;" :: "r"(dst), "l"(src));
}
__device__ __forceinline__ void cp_commit() {
    asm volatile("cp.async.commit_group;" ::: "memory");
}
template <int W> __device__ __forceinline__ void cp_wait() {
    asm volatile("cp.async.wait_group %0;" :: "n"(W) : "memory");
}
__device__ __forceinline__ uint32_t packh(__half a, __half b) {
    __half2 t; t.x = a; t.y = b;
    uint32_t u; *(__half2*)&u = t; return u;
}

// ---------------- plain fp16 GEMM, BK=32, 4-stage, batched LDSM ---------------
template <bool WF32>
__global__ __launch_bounds__(256, 2) void gemm_plain32(
    const __half* __restrict__ A, const __half* __restrict__ B,
    const float* __restrict__ bias,
    float* __restrict__ C, __half* __restrict__ Ch,
    int K, int lda, int ldb, int ldc, int qlim, float qscale)
{
    extern __shared__ char smem[];
    const int tid = threadIdx.x;
    const int m0 = blockIdx.y * BM, n0 = blockIdx.x * BN;
    const int nt = K >> 5;

    const uint32_t S0 = smem_u32(smem);
    const int rb  = tid >> 1;
    const int cb0 = (tid & 1) * 2;

    auto copy_stage = [&](int kt) {
        const uint32_t base = S0 + (uint32_t)(kt & 3) * 16384;
        const int k0 = kt << 5;
#pragma unroll
        for (int j = 0; j < 2; ++j) {
            int c = cb0 + j;
            uint32_t sw = rb * 64 + ((c ^ ((rb >> 1) & 3)) << 4);
            cp16(base + sw,        A + (size_t)(m0 + rb) * lda + k0 + c * 8);
            cp16(base + 8192 + sw, B + (size_t)(n0 + rb) * ldb + k0 + c * 8);
        }
    };

    const int warp = tid >> 5, lane = tid & 31;
    const int wm = warp >> 1, wn = warp & 1;
    const int rselA = (lane & 7) + (((lane >> 3) & 1) << 3);
    const int chA   = (lane >> 4) & 1;
    const int rselB = (lane & 7) + (((lane >> 4) & 1) << 3);
    const int chB   = (lane >> 3) & 1;

    float acc[2][8][4];
#pragma unroll
    for (int a = 0; a < 2; ++a)
#pragma unroll
        for (int b = 0; b < 8; ++b)
#pragma unroll
            for (int c = 0; c < 4; ++c) acc[a][b][c] = 0.f;

    auto compute_tile = [&](int buf) {
        const uint32_t abase = S0 + (uint32_t)buf * 16384;
        const uint32_t bbase = abase + 8192;
#pragma unroll
        for (int ks = 0; ks < 2; ++ks) {
            // batch ALL fragment loads (MLP=6), then the 16-MMA burst
            uint32_t aH[2][4], bh[4][4];
            const int g = 2 * ks + chA;
#pragma unroll
            for (int mf = 0; mf < 2; ++mf) {
                int row = wm * 32 + mf * 16 + rselA;
                ldsm_x4(aH[mf], abase + row * 64 + ((g ^ ((row >> 1) & 3)) << 4));
            }
            const int gb = 2 * ks + chB;
#pragma unroll
            for (int np = 0; np < 4; ++np) {
                int rowb = wn * 64 + np * 16 + rselB;
                ldsm_x4(bh[np], bbase + rowb * 64 + ((gb ^ ((rowb >> 1) & 3)) << 4));
            }
#pragma unroll
            for (int np = 0; np < 4; ++np)
#pragma unroll
                for (int mf = 0; mf < 2; ++mf) {
                    mma_f16(acc[mf][2 * np],     aH[mf], bh[np]);
                    mma_f16(acc[mf][2 * np + 1], aH[mf], bh[np] + 2);
                }
        }
    };

    // 4-stage ring, copy-ahead 3
    copy_stage(0); cp_commit();
    if (nt > 1) { copy_stage(1); cp_commit(); }
    if (nt > 2) { copy_stage(2); cp_commit(); }
    for (int kt = 0; kt < nt; ++kt) {
        const int pend = (nt - 1 - kt < 2) ? (nt - 1 - kt) : 2;
        if (pend == 2) cp_wait<2>(); else if (pend == 1) cp_wait<1>(); else cp_wait<0>();
        __syncthreads();
        if (kt + 3 < nt) { copy_stage(kt + 3); cp_commit(); }
        compute_tile(kt & 3);
    }

#pragma unroll
    for (int mf = 0; mf < 2; ++mf) {
        int row = m0 + wm * 32 + mf * 16 + (lane >> 2);
#pragma unroll
        for (int nf = 0; nf < 8; ++nf) {
            int col = n0 + wn * 64 + nf * 8 + (lane & 3) * 2;
            float b0 = bias[col], b1 = bias[col + 1];
            float sc = (col < qlim) ? qscale : 1.0f;
            float v0 = (acc[mf][nf][0] + b0) * sc, v1 = (acc[mf][nf][1] + b1) * sc;
            float v2 = (acc[mf][nf][2] + b0) * sc, v3 = (acc[mf][nf][3] + b1) * sc;
            size_t o0 = (size_t)row * ldc + col;
            size_t o1 = (size_t)(row + 8) * ldc + col;
            if (WF32) {
                *(float2*)(C + o0) = make_float2(v0, v1);
                *(float2*)(C + o1) = make_float2(v2, v3);
            } else {
                *(uint32_t*)(Ch + o0) = packh(__float2half_rn(v0), __float2half_rn(v1));
                *(uint32_t*)(Ch + o1) = packh(__float2half_rn(v2), __float2half_rn(v3));
            }
        }
    }
}

// ---------------- fused flash attention (Q pre-scaled; exp2 softmax) ----------
__global__ __launch_bounds__(256) void flash_attn(
    const __half* __restrict__ qkvh, __half* __restrict__ outh)
{
    const int qi = 15 - (int)blockIdx.x;
    const int bh = blockIdx.y;
    const int b = bh >> 4, h = bh & 15;
    const int q0 = qi * 128;
    const size_t base = (size_t)b * SEQ * 6144 + (size_t)h * 128;
    const __half* Qp = qkvh + base;
    const __half* Kp = qkvh + base + 2048;
    const __half* Vp = qkvh + base + 4096;

    extern __shared__ char smem[];
    const uint32_t S0 = smem_u32(smem);
    const int tid = threadIdx.x, lane = tid & 31, warp = tid >> 5;

#pragma unroll
    for (int i = 0; i < 8; ++i) {
        int idx = tid + i * 256;
        int row = idx >> 4, c = idx & 15, p = c >> 3, c8 = c & 7;
        cp16(S0 + p * 16384 + row * 128 + ((c8 ^ (row & 7)) << 4),
             Qp + (size_t)(q0 + row) * 6144 + p * 64 + c8 * 8);
    }
    cp_commit();

    auto copy_kv = [&](int t) {
        const uint32_t sb = S0 + 32768 + (uint32_t)(t & 1) * 32768;
        const int kv0 = t * 64;
#pragma unroll
        for (int q = 0; q < 2; ++q) {
            const __half* src = q ? Vp : Kp;
#pragma unroll
            for (int i = 0; i < 4; ++i) {
                int idx = tid + i * 256;
                int row = idx >> 4, c = idx & 15, p = c >> 3, c8 = c & 7;
                cp16(sb + q * 16384 + p * 8192 + row * 128 + ((c8 ^ (row & 7)) << 4),
                     src + (size_t)(kv0 + row) * 6144 + p * 64 + c8 * 8);
            }
        }
    };

    const int rselA = (lane & 7) + (((lane >> 3) & 1) << 3);
    const int chA   = (lane >> 4) & 1;
    const int rselB = (lane & 7) + (((lane >> 4) & 1) << 3);
    const int chB   = (lane >> 3) & 1;
    const int qr = warp * 16;

    const int nt = 2 * qi + 2;
    copy_kv(0); cp_commit();
    if (nt > 1) { copy_kv(1); cp_commit(); }

    cp_wait<2>();
    __syncthreads();
    uint32_t qf[8][4];
#pragma unroll
    for (int ks = 0; ks < 8; ++ks) {
        int row = qr + rselA;
        int g = ks * 2 + chA, p = g >> 3, c8 = g & 7;
        ldsm_x4(qf[ks], S0 + (uint32_t)p * 16384 + row * 128 + ((c8 ^ (row & 7)) << 4));
    }

    float m0 = -1e30f, m1 = -1e30f, l0 = 0.f, l1 = 0.f;
    float accO[16][4];
#pragma unroll
    for (int j = 0; j < 16; ++j)
#pragma unroll
        for (int c = 0; c < 4; ++c) accO[j][c] = 0.f;

    for (int t = 0; t < nt; ++t) {
        if (t + 1 < nt) cp_wait<1>(); else cp_wait<0>();
        __syncthreads();

        const uint32_t sb = S0 + 32768 + (uint32_t)(t & 1) * 32768;
        const uint32_t sK = sb, sV = sb + 16384;

        float accS[8][4];
#pragma unroll
        for (int j = 0; j < 8; ++j)
#pragma unroll
            for (int c = 0; c < 4; ++c) accS[j][c] = 0.f;

#pragma unroll
        for (int ks = 0; ks < 8; ++ks) {
            uint32_t bH[4][4];
            const int g = ks * 2 + chB, p = g >> 3, c8 = g & 7;
#pragma unroll
            for (int n2 = 0; n2 < 4; ++n2) {
                int row = n2 * 16 + rselB;
                ldsm_x4(bH[n2], sK + (uint32_t)p * 8192 + row * 128 + ((c8 ^ (row & 7)) << 4));
            }
#pragma unroll
            for (int n2 = 0; n2 < 4; ++n2) {
                mma_f16(accS[2 * n2],     qf[ks], bH[n2]);
                mma_f16(accS[2 * n2 + 1], qf[ks], bH[n2] + 2);
            }
        }

        const int kv0 = t * 64;
        const int grow0 = q0 + qr + (lane >> 2);
        const int grow1 = grow0 + 8;
        const bool masked = (t >= 2 * qi);
        if (masked) {
#pragma unroll
            for (int nf = 0; nf < 8; ++nf) {
                int col = kv0 + nf * 8 + (lane & 3) * 2;
                if (col     > grow0) accS[nf][0] = -1e30f;
                if (col + 1 > grow0) accS[nf][1] = -1e30f;
                if (col     > grow1) accS[nf][2] = -1e30f;
                if (col + 1 > grow1) accS[nf][3] = -1e30f;
            }
        }
        float mx0 = -1e30f, mx1 = -1e30f;
#pragma unroll
        for (int nf = 0; nf < 8; ++nf) {
            mx0 = fmaxf(mx0, fmaxf(accS[nf][0], accS[nf][1]));
            mx1 = fmaxf(mx1, fmaxf(accS[nf][2], accS[nf][3]));
        }
        mx0 = fmaxf(mx0, __shfl_xor_sync(0xffffffffu, mx0, 1));
        mx0 = fmaxf(mx0, __shfl_xor_sync(0xffffffffu, mx0, 2));
        mx1 = fmaxf(mx1, __shfl_xor_sync(0xffffffffu, mx1, 1));
        mx1 = fmaxf(mx1, __shfl_xor_sync(0xffffffffu, mx1, 2));
        const float nm0 = fmaxf(m0, mx0), nm1 = fmaxf(m1, mx1);
        const float cr0 = exp2f(m0 - nm0), cr1 = exp2f(m1 - nm1);
        m0 = nm0; m1 = nm1;

        float rs0 = 0.f, rs1 = 0.f;
        uint32_t phr[8], phr8[8];
#pragma unroll
        for (int nf = 0; nf < 8; ++nf) {
            float p0 = exp2f(accS[nf][0] - nm0), p1 = exp2f(accS[nf][1] - nm0);
            float p2 = exp2f(accS[nf][2] - nm1), p3 = exp2f(accS[nf][3] - nm1);
            rs0 += p0 + p1; rs1 += p2 + p3;
            phr[nf]  = packh(__float2half_rn(p0), __float2half_rn(p1));
            phr8[nf] = packh(__float2half_rn(p2), __float2half_rn(p3));
        }
        rs0 += __shfl_xor_sync(0xffffffffu, rs0, 1);
        rs0 += __shfl_xor_sync(0xffffffffu, rs0, 2);
        rs1 += __shfl_xor_sync(0xffffffffu, rs1, 1);
        rs1 += __shfl_xor_sync(0xffffffffu, rs1, 2);
        l0 = l0 * cr0 + rs0;
        l1 = l1 * cr1 + rs1;
#pragma unroll
        for (int j = 0; j < 16; ++j) {
            accO[j][0] *= cr0; accO[j][1] *= cr0;
            accO[j][2] *= cr1; accO[j][3] *= cr1;
        }

#pragma unroll
        for (int ks = 0; ks < 4; ++ks) {
            uint32_t Aph[4] = {phr[2 * ks], phr8[2 * ks], phr[2 * ks + 1], phr8[2 * ks + 1]};
            const int rowv = ks * 16 + (lane & 15);
            uint32_t vf[4][2][4];
#pragma unroll
            for (int jj = 0; jj < 4; ++jj) {
                {
                    int cv = 4 * jj + (lane >> 4), p = cv >> 3, c8 = cv & 7;
                    ldsm_x4_t(vf[jj][0], sV + (uint32_t)p * 8192 + rowv * 128 + ((c8 ^ (rowv & 7)) << 4));
                }
                {
                    int cv = 4 * jj + 2 + (lane >> 4), p = cv >> 3, c8 = cv & 7;
                    ldsm_x4_t(vf[jj][1], sV + (uint32_t)p * 8192 + rowv * 128 + ((c8 ^ (rowv & 7)) << 4));
                }
            }
#pragma unroll
            for (int jj = 0; jj < 4; ++jj) {
                mma_f16(accO[4 * jj],     Aph, vf[jj][0]);
                mma_f16(accO[4 * jj + 1], Aph, vf[jj][0] + 2);
                mma_f16(accO[4 * jj + 2], Aph, vf[jj][1]);
                mma_f16(accO[4 * jj + 3], Aph, vf[jj][1] + 2);
            }
        }

        __syncthreads();
        if (t + 2 < nt) { copy_kv(t + 2); cp_commit(); }
    }

    const float i0 = 1.f / l0, i1 = 1.f / l1;
    const size_t obase = (size_t)b * SEQ * N_EMBD + (size_t)h * 128;
    const int row0 = q0 + qr + (lane >> 2);
#pragma unroll
    for (int j = 0; j < 16; ++j) {
        int d = j * 8 + (lane & 3) * 2;
        size_t o0 = obase + (size_t)row0 * N_EMBD + d;
        size_t o1 = obase + (size_t)(row0 + 8) * N_EMBD + d;
        *(uint32_t*)(outh + o0) = packh(__float2half_rn(accO[j][0] * i0),
                                        __float2half_rn(accO[j][1] * i0));
        *(uint32_t*)(outh + o1) = packh(__float2half_rn(accO[j][2] * i1),
                                        __float2half_rn(accO[j][3] * i1));
    }
}

// ---------------- converts ----------------------------------------------------
__global__ __launch_bounds__(256) void convert_plain4(
    const float* __restrict__ in, __half* __restrict__ oh, int n4)
{
    for (int i = blockIdx.x * 256 + threadIdx.x; i < n4; i += gridDim.x * 256) {
        float4 v = ((const float4*)in)[i];
        uint32_t lo = packh(__float2half_rn(v.x), __float2half_rn(v.y));
        uint32_t hi = packh(__float2half_rn(v.z), __float2half_rn(v.w));
        ((uint2*)oh)[i] = make_uint2(lo, hi);
    }
}
__global__ __launch_bounds__(256) void transpose_w(
    const float* __restrict__ in, __half* __restrict__ out, int ld_in, int ld_out)
{
    __shared__ float t[32][33];
    const int c0 = blockIdx.x * 32, r0 = blockIdx.y * 32;
    const int tx = threadIdx.x, ty = threadIdx.y;
#pragma unroll
    for (int j = 0; j < 32; j += 8)
        t[ty + j][tx] = in[(size_t)(r0 + ty + j) * ld_in + c0 + tx];
    __syncthreads();
#pragma unroll
    for (int j = 0; j < 32; j += 8)
        out[(size_t)(c0 + ty + j) * ld_out + r0 + tx] = __float2half_rn(t[tx][ty + j]);
}

// ---------------- launch ------------------------------------------------------
extern "C" void kernel_launch(void* const* d_in, const int* in_sizes, int n_in,
                              void* d_out, int out_size)
{
    const float* x     = (const float*)d_in[0];
    const float* Wqkv  = (const float*)d_in[1];
    const float* bqkv  = (const float*)d_in[2];
    const float* Wproj = (const float*)d_in[3];
    const float* bproj = (const float*)d_in[4];
    float* out = (float*)d_out;

    __half *x_h, *wq, *wp, *qkv_h, *at_h;
    cudaGetSymbolAddress((void**)&x_h, g_x_h);
    cudaGetSymbolAddress((void**)&wq, g_wqkvT);
    cudaGetSymbolAddress((void**)&wp, g_wprojT);
    cudaGetSymbolAddress((void**)&qkv_h, g_qkv_h);
    cudaGetSymbolAddress((void**)&at_h, g_attn_h);

    const int GEMM_SMEM  = 65536;    // 4 stages x 16KB
    const int FLASH_SMEM = 98304;    // Q 32KB + 2 stages x 32KB
    cudaFuncSetAttribute(gemm_plain32<false>,
                         cudaFuncAttributeMaxDynamicSharedMemorySize, GEMM_SMEM);
    cudaFuncSetAttribute(gemm_plain32<true>,
                         cudaFuncAttributeMaxDynamicSharedMemorySize, GEMM_SMEM);
    cudaFuncSetAttribute(flash_attn,
                         cudaFuncAttributeMaxDynamicSharedMemorySize, FLASH_SMEM);

    const int M = BATCH * SEQ, E = N_EMBD, E3 = 3 * N_EMBD;
    const float qscale = 0.12751743056057344f;  // 1/sqrt(128) * log2(e)

    convert_plain4<<<4096, 256>>>(x, x_h, M * E / 4);
    transpose_w<<<dim3(E3 / 32, E / 32), dim3(32, 8)>>>(Wqkv, wq, E3, E);
    transpose_w<<<dim3(E / 32, E / 32), dim3(32, 8)>>>(Wproj, wp, E, E);

    gemm_plain32<false><<<dim3(E3 / BN, M / BM), 256, GEMM_SMEM>>>(
        x_h, wq, bqkv, nullptr, qkv_h, E, E, E, E3, 2048, qscale);

    flash_attn<<<dim3(SEQ / 128, BATCH * N_HEAD), 256, FLASH_SMEM>>>(qkv_h, at_h);

    gemm_plain32<true><<<dim3(E / BN, M / BM), 256, GEMM_SMEM>>>(
        at_h, wp, bproj, out, nullptr, E, E, E, E, 0, 1.0f);
}

// round 17
// speedup vs baseline: 1.3590x; 1.0007x over previous
#include <cuda_runtime.h>
#include <cuda_fp16.h>
#include <cstdint>

#define N_EMBD 2048
#define N_HEAD 16
#define HEAD_DIM 128
#define BATCH 2
#define SEQ 2048

#define BM 128
#define BN 128

// ---------------- scratch ----------------------------------------------------
__device__ __half g_x_h[(size_t)BATCH * SEQ * N_EMBD];
__device__ __half g_wqkvT[(size_t)3 * N_EMBD * N_EMBD];
__device__ __half g_wprojT[(size_t)N_EMBD * N_EMBD];
__device__ __half g_qkv_h[(size_t)BATCH * SEQ * 3 * N_EMBD];
__device__ __half g_attn_h[(size_t)BATCH * SEQ * N_EMBD];

// ---------------- PTX helpers -------------------------------------------------
__device__ __forceinline__ uint32_t smem_u32(const void* p) {
    return (uint32_t)__cvta_generic_to_shared(p);
}
__device__ __forceinline__ void ldsm_x4(uint32_t* r, uint32_t addr) {
    asm volatile("ldmatrix.sync.aligned.m8n8.x4.shared.b16 {%0,%1,%2,%3}, [%4];"
                 : "=r"(r[0]), "=r"(r[1]), "=r"(r[2]), "=r"(r[3]) : "r"(addr));
}
__device__ __forceinline__ void ldsm_x4_t(uint32_t* r, uint32_t addr) {
    asm volatile("ldmatrix.sync.aligned.m8n8.x4.trans.shared.b16 {%0,%1,%2,%3}, [%4];"
                 : "=r"(r[0]), "=r"(r[1]), "=r"(r[2]), "=r"(r[3]) : "r"(addr));
}
__device__ __forceinline__ void mma_f16(float* d, const uint32_t* a, const uint32_t* b) {
    asm volatile(
        "mma.sync.aligned.m16n8k16.row.col.f32.f16.f16.f32 "
        "{%0,%1,%2,%3},{%4,%5,%6,%7},{%8,%9},{%0,%1,%2,%3};"
        : "+f"(d[0]), "+f"(d[1]), "+f"(d[2]), "+f"(d[3])
        : "r"(a[0]), "r"(a[1]), "r"(a[2]), "r"(a[3]), "r"(b[0]), "r"(b[1]));
}
__device__ __forceinline__ void cp16(uint32_t dst, const void* src) {
    asm volatile("cp.async.cg.shared.global [%0], [%1], 16;" :: "r"(dst), "l"(src));
}
__device__ __forceinline__ void cp_commit() {
    asm volatile("cp.async.commit_group;" ::: "memory");
}
template <int W> __device__ __forceinline__ void cp_wait() {
    asm volatile("cp.async.wait_group %0;" :: "n"(W) : "memory");
}
__device__ __forceinline__ uint32_t packh(__half a, __half b) {
    __half2 t; t.x = a; t.y = b;
    uint32_t u; *(__half2*)&u = t; return u;
}

// ---------------- plain fp16 GEMM, BK=32, 6-stage ring, 1 sync / 2 tiles ------
template <bool WF32>
__global__ __launch_bounds__(256, 2) void gemm_plain32(
    const __half* __restrict__ A, const __half* __restrict__ B,
    const float* __restrict__ bias,
    float* __restrict__ C, __half* __restrict__ Ch,
    int K, int lda, int ldb, int ldc, int qlim, float qscale)
{
    extern __shared__ char smem[];
    const int tid = threadIdx.x;
    const int m0 = blockIdx.y * BM, n0 = blockIdx.x * BN;
    const int nt = K >> 5;                 // even for all our K

    const uint32_t S0 = smem_u32(smem);
    const int rb  = tid >> 1;
    const int cb0 = (tid & 1) * 2;

    auto copy_stage = [&](int kt) {
        const uint32_t base = S0 + (uint32_t)(kt % 6) * 16384;
        const int k0 = kt << 5;
#pragma unroll
        for (int j = 0; j < 2; ++j) {
            int c = cb0 + j;
            uint32_t sw = rb * 64 + ((c ^ ((rb >> 1) & 3)) << 4);
            cp16(base + sw,        A + (size_t)(m0 + rb) * lda + k0 + c * 8);
            cp16(base + 8192 + sw, B + (size_t)(n0 + rb) * ldb + k0 + c * 8);
        }
    };

    const int warp = tid >> 5, lane = tid & 31;
    const int wm = warp >> 1, wn = warp & 1;
    const int rselA = (lane & 7) + (((lane >> 3) & 1) << 3);
    const int chA   = (lane >> 4) & 1;
    const int rselB = (lane & 7) + (((lane >> 4) & 1) << 3);
    const int chB   = (lane >> 3) & 1;

    float acc[2][8][4];
#pragma unroll
    for (int a = 0; a < 2; ++a)
#pragma unroll
        for (int b = 0; b < 8; ++b)
#pragma unroll
            for (int c = 0; c < 4; ++c) acc[a][b][c] = 0.f;

    auto compute_tile = [&](int buf) {
        const uint32_t abase = S0 + (uint32_t)buf * 16384;
        const uint32_t bbase = abase + 8192;
#pragma unroll
        for (int ks = 0; ks < 2; ++ks) {
            uint32_t aH[2][4], bh[4][4];
            const int g = 2 * ks + chA;
#pragma unroll
            for (int mf = 0; mf < 2; ++mf) {
                int row = wm * 32 + mf * 16 + rselA;
                ldsm_x4(aH[mf], abase + row * 64 + ((g ^ ((row >> 1) & 3)) << 4));
            }
            const int gb = 2 * ks + chB;
#pragma unroll
            for (int np = 0; np < 4; ++np) {
                int rowb = wn * 64 + np * 16 + rselB;
                ldsm_x4(bh[np], bbase + rowb * 64 + ((gb ^ ((rowb >> 1) & 3)) << 4));
            }
#pragma unroll
            for (int np = 0; np < 4; ++np)
#pragma unroll
                for (int mf = 0; mf < 2; ++mf) {
                    mma_f16(acc[mf][2 * np],     aH[mf], bh[np]);
                    mma_f16(acc[mf][2 * np + 1], aH[mf], bh[np] + 2);
                }
        }
    };

    // preload 4 stages
    copy_stage(0); cp_commit();
    if (nt > 1) { copy_stage(1); cp_commit(); }
    if (nt > 2) { copy_stage(2); cp_commit(); }
    if (nt > 3) { copy_stage(3); cp_commit(); }

    // 2 tiles per barrier
    for (int kt = 0; kt < nt; kt += 2) {
        int pend = nt - kt - 2; if (pend > 2) pend = 2; if (pend < 0) pend = 0;
        if (pend == 2) cp_wait<2>(); else if (pend == 1) cp_wait<1>(); else cp_wait<0>();
        __syncthreads();
        if (kt + 4 < nt) { copy_stage(kt + 4); cp_commit(); }
        if (kt + 5 < nt) { copy_stage(kt + 5); cp_commit(); }
        compute_tile(kt % 6);
        compute_tile((kt + 1) % 6);
    }

#pragma unroll
    for (int mf = 0; mf < 2; ++mf) {
        int row = m0 + wm * 32 + mf * 16 + (lane >> 2);
#pragma unroll
        for (int nf = 0; nf < 8; ++nf) {
            int col = n0 + wn * 64 + nf * 8 + (lane & 3) * 2;
            float b0 = bias[col], b1 = bias[col + 1];
            float sc = (col < qlim) ? qscale : 1.0f;
            float v0 = (acc[mf][nf][0] + b0) * sc, v1 = (acc[mf][nf][1] + b1) * sc;
            float v2 = (acc[mf][nf][2] + b0) * sc, v3 = (acc[mf][nf][3] + b1) * sc;
            size_t o0 = (size_t)row * ldc + col;
            size_t o1 = (size_t)(row + 8) * ldc + col;
            if (WF32) {
                *(float2*)(C + o0) = make_float2(v0, v1);
                *(float2*)(C + o1) = make_float2(v2, v3);
            } else {
                *(uint32_t*)(Ch + o0) = packh(__float2half_rn(v0), __float2half_rn(v1));
                *(uint32_t*)(Ch + o1) = packh(__float2half_rn(v2), __float2half_rn(v3));
            }
        }
    }
}

// ---------------- fused flash attention (Q pre-scaled; exp2 softmax) ----------
__global__ __launch_bounds__(256) void flash_attn(
    const __half* __restrict__ qkvh, __half* __restrict__ outh)
{
    const int qi = 15 - (int)blockIdx.x;
    const int bh = blockIdx.y;
    const int b = bh >> 4, h = bh & 15;
    const int q0 = qi * 128;
    const size_t base = (size_t)b * SEQ * 6144 + (size_t)h * 128;
    const __half* Qp = qkvh + base;
    const __half* Kp = qkvh + base + 2048;
    const __half* Vp = qkvh + base + 4096;

    extern __shared__ char smem[];
    const uint32_t S0 = smem_u32(smem);
    const int tid = threadIdx.x, lane = tid & 31, warp = tid >> 5;

#pragma unroll
    for (int i = 0; i < 8; ++i) {
        int idx = tid + i * 256;
        int row = idx >> 4, c = idx & 15, p = c >> 3, c8 = c & 7;
        cp16(S0 + p * 16384 + row * 128 + ((c8 ^ (row & 7)) << 4),
             Qp + (size_t)(q0 + row) * 6144 + p * 64 + c8 * 8);
    }
    cp_commit();

    auto copy_kv = [&](int t) {
        const uint32_t sb = S0 + 32768 + (uint32_t)(t & 1) * 32768;
        const int kv0 = t * 64;
#pragma unroll
        for (int q = 0; q < 2; ++q) {
            const __half* src = q ? Vp : Kp;
#pragma unroll
            for (int i = 0; i < 4; ++i) {
                int idx = tid + i * 256;
                int row = idx >> 4, c = idx & 15, p = c >> 3, c8 = c & 7;
                cp16(sb + q * 16384 + p * 8192 + row * 128 + ((c8 ^ (row & 7)) << 4),
                     src + (size_t)(kv0 + row) * 6144 + p * 64 + c8 * 8);
            }
        }
    };

    const int rselA = (lane & 7) + (((lane >> 3) & 1) << 3);
    const int chA   = (lane >> 4) & 1;
    const int rselB = (lane & 7) + (((lane >> 4) & 1) << 3);
    const int chB   = (lane >> 3) & 1;
    const int qr = warp * 16;

    const int nt = 2 * qi + 2;
    copy_kv(0); cp_commit();
    if (nt > 1) { copy_kv(1); cp_commit(); }

    cp_wait<2>();
    __syncthreads();
    uint32_t qf[8][4];
#pragma unroll
    for (int ks = 0; ks < 8; ++ks) {
        int row = qr + rselA;
        int g = ks * 2 + chA, p = g >> 3, c8 = g & 7;
        ldsm_x4(qf[ks], S0 + (uint32_t)p * 16384 + row * 128 + ((c8 ^ (row & 7)) << 4));
    }

    float m0 = -1e30f, m1 = -1e30f, l0 = 0.f, l1 = 0.f;
    float accO[16][4];
#pragma unroll
    for (int j = 0; j < 16; ++j)
#pragma unroll
        for (int c = 0; c < 4; ++c) accO[j][c] = 0.f;

    for (int t = 0; t < nt; ++t) {
        if (t + 1 < nt) cp_wait<1>(); else cp_wait<0>();
        __syncthreads();

        const uint32_t sb = S0 + 32768 + (uint32_t)(t & 1) * 32768;
        const uint32_t sK = sb, sV = sb + 16384;

        float accS[8][4];
#pragma unroll
        for (int j = 0; j < 8; ++j)
#pragma unroll
            for (int c = 0; c < 4; ++c) accS[j][c] = 0.f;

#pragma unroll
        for (int ks = 0; ks < 8; ++ks) {
            uint32_t bH[4][4];
            const int g = ks * 2 + chB, p = g >> 3, c8 = g & 7;
#pragma unroll
            for (int n2 = 0; n2 < 4; ++n2) {
                int row = n2 * 16 + rselB;
                ldsm_x4(bH[n2], sK + (uint32_t)p * 8192 + row * 128 + ((c8 ^ (row & 7)) << 4));
            }
#pragma unroll
            for (int n2 = 0; n2 < 4; ++n2) {
                mma_f16(accS[2 * n2],     qf[ks], bH[n2]);
                mma_f16(accS[2 * n2 + 1], qf[ks], bH[n2] + 2);
            }
        }

        const int kv0 = t * 64;
        const int grow0 = q0 + qr + (lane >> 2);
        const int grow1 = grow0 + 8;
        const bool masked = (t >= 2 * qi);
        if (masked) {
#pragma unroll
            for (int nf = 0; nf < 8; ++nf) {
                int col = kv0 + nf * 8 + (lane & 3) * 2;
                if (col     > grow0) accS[nf][0] = -1e30f;
                if (col + 1 > grow0) accS[nf][1] = -1e30f;
                if (col     > grow1) accS[nf][2] = -1e30f;
                if (col + 1 > grow1) accS[nf][3] = -1e30f;
            }
        }
        float mx0 = -1e30f, mx1 = -1e30f;
#pragma unroll
        for (int nf = 0; nf < 8; ++nf) {
            mx0 = fmaxf(mx0, fmaxf(accS[nf][0], accS[nf][1]));
            mx1 = fmaxf(mx1, fmaxf(accS[nf][2], accS[nf][3]));
        }
        mx0 = fmaxf(mx0, __shfl_xor_sync(0xffffffffu, mx0, 1));
        mx0 = fmaxf(mx0, __shfl_xor_sync(0xffffffffu, mx0, 2));
        mx1 = fmaxf(mx1, __shfl_xor_sync(0xffffffffu, mx1, 1));
        mx1 = fmaxf(mx1, __shfl_xor_sync(0xffffffffu, mx1, 2));
        const float nm0 = fmaxf(m0, mx0), nm1 = fmaxf(m1, mx1);
        const float cr0 = exp2f(m0 - nm0), cr1 = exp2f(m1 - nm1);
        m0 = nm0; m1 = nm1;

        float rs0 = 0.f, rs1 = 0.f;
        uint32_t phr[8], phr8[8];
#pragma unroll
        for (int nf = 0; nf < 8; ++nf) {
            float p0 = exp2f(accS[nf][0] - nm0), p1 = exp2f(accS[nf][1] - nm0);
            float p2 = exp2f(accS[nf][2] - nm1), p3 = exp2f(accS[nf][3] - nm1);
            rs0 += p0 + p1; rs1 += p2 + p3;
            phr[nf]  = packh(__float2half_rn(p0), __float2half_rn(p1));
            phr8[nf] = packh(__float2half_rn(p2), __float2half_rn(p3));
        }
        rs0 += __shfl_xor_sync(0xffffffffu, rs0, 1);
        rs0 += __shfl_xor_sync(0xffffffffu, rs0, 2);
        rs1 += __shfl_xor_sync(0xffffffffu, rs1, 1);
        rs1 += __shfl_xor_sync(0xffffffffu, rs1, 2);
        l0 = l0 * cr0 + rs0;
        l1 = l1 * cr1 + rs1;
#pragma unroll
        for (int j = 0; j < 16; ++j) {
            accO[j][0] *= cr0; accO[j][1] *= cr0;
            accO[j][2] *= cr1; accO[j][3] *= cr1;
        }

#pragma unroll
        for (int ks = 0; ks < 4; ++ks) {
            uint32_t Aph[4] = {phr[2 * ks], phr8[2 * ks], phr[2 * ks + 1], phr8[2 * ks + 1]};
            const int rowv = ks * 16 + (lane & 15);
            uint32_t vf[4][2][4];
#pragma unroll
            for (int jj = 0; jj < 4; ++jj) {
                {
                    int cv = 4 * jj + (lane >> 4), p = cv >> 3, c8 = cv & 7;
                    ldsm_x4_t(vf[jj][0], sV + (uint32_t)p * 8192 + rowv * 128 + ((c8 ^ (rowv & 7)) << 4));
                }
                {
                    int cv = 4 * jj + 2 + (lane >> 4), p = cv >> 3, c8 = cv & 7;
                    ldsm_x4_t(vf[jj][1], sV + (uint32_t)p * 8192 + rowv * 128 + ((c8 ^ (rowv & 7)) << 4));
                }
            }
#pragma unroll
            for (int jj = 0; jj < 4; ++jj) {
                mma_f16(accO[4 * jj],     Aph, vf[jj][0]);
                mma_f16(accO[4 * jj + 1], Aph, vf[jj][0] + 2);
                mma_f16(accO[4 * jj + 2], Aph, vf[jj][1]);
                mma_f16(accO[4 * jj + 3], Aph, vf[jj][1] + 2);
            }
        }

        __syncthreads();
        if (t + 2 < nt) { copy_kv(t + 2); cp_commit(); }
    }

    const float i0 = 1.f / l0, i1 = 1.f / l1;
    const size_t obase = (size_t)b * SEQ * N_EMBD + (size_t)h * 128;
    const int row0 = q0 + qr + (lane >> 2);
#pragma unroll
    for (int j = 0; j < 16; ++j) {
        int d = j * 8 + (lane & 3) * 2;
        size_t o0 = obase + (size_t)row0 * N_EMBD + d;
        size_t o1 = obase + (size_t)(row0 + 8) * N_EMBD + d;
        *(uint32_t*)(outh + o0) = packh(__float2half_rn(accO[j][0] * i0),
                                        __float2half_rn(accO[j][1] * i0));
        *(uint32_t*)(outh + o1) = packh(__float2half_rn(accO[j][2] * i1),
                                        __float2half_rn(accO[j][3] * i1));
    }
}

// ---------------- converts ----------------------------------------------------
__global__ __launch_bounds__(256) void convert_plain4(
    const float* __restrict__ in, __half* __restrict__ oh, int n4)
{
    for (int i = blockIdx.x * 256 + threadIdx.x; i < n4; i += gridDim.x * 256) {
        float4 v = ((const float4*)in)[i];
        uint32_t lo = packh(__float2half_rn(v.x), __float2half_rn(v.y));
        uint32_t hi = packh(__float2half_rn(v.z), __float2half_rn(v.w));
        ((uint2*)oh)[i] = make_uint2(lo, hi);
    }
}
__global__ __launch_bounds__(256) void transpose_w(
    const float* __restrict__ in, __half* __restrict__ out, int ld_in, int ld_out)
{
    __shared__ float t[32][33];
    const int c0 = blockIdx.x * 32, r0 = blockIdx.y * 32;
    const int tx = threadIdx.x, ty = threadIdx.y;
#pragma unroll
    for (int j = 0; j < 32; j += 8)
        t[ty + j][tx] = in[(size_t)(r0 + ty + j) * ld_in + c0 + tx];
    __syncthreads();
#pragma unroll
    for (int j = 0; j < 32; j += 8)
        out[(size_t)(c0 + ty + j) * ld_out + r0 + tx] = __float2half_rn(t[tx][ty + j]);
}

// ---------------- launch ------------------------------------------------------
extern "C" void kernel_launch(void* const* d_in, const int* in_sizes, int n_in,
                              void* d_out, int out_size)
{
    const float* x     = (const float*)d_in[0];
    const float* Wqkv  = (const float*)d_in[1];
    const float* bqkv  = (const float*)d_in[2];
    const float* Wproj = (const float*)d_in[3];
    const float* bproj = (const float*)d_in[4];
    float* out = (float*)d_out;

    __half *x_h, *wq, *wp, *qkv_h, *at_h;
    cudaGetSymbolAddress((void**)&x_h, g_x_h);
    cudaGetSymbolAddress((void**)&wq, g_wqkvT);
    cudaGetSymbolAddress((void**)&wp, g_wprojT);
    cudaGetSymbolAddress((void**)&qkv_h, g_qkv_h);
    cudaGetSymbolAddress((void**)&at_h, g_attn_h);

    const int GEMM_SMEM  = 98304;    // 6 stages x 16KB; 2 CTAs/SM = 192KB
    const int FLASH_SMEM = 98304;    // Q 32KB + 2 stages x 32KB
    cudaFuncSetAttribute(gemm_plain32<false>,
                         cudaFuncAttributeMaxDynamicSharedMemorySize, GEMM_SMEM);
    cudaFuncSetAttribute(gemm_plain32<true>,
                         cudaFuncAttributeMaxDynamicSharedMemorySize, GEMM_SMEM);
    cudaFuncSetAttribute(flash_attn,
                         cudaFuncAttributeMaxDynamicSharedMemorySize, FLASH_SMEM);

    const int M = BATCH * SEQ, E = N_EMBD, E3 = 3 * N_EMBD;
    const float qscale = 0.12751743056057344f;  // 1/sqrt(128) * log2(e)

    convert_plain4<<<4096, 256>>>(x, x_h, M * E / 4);
    transpose_w<<<dim3(E3 / 32, E / 32), dim3(32, 8)>>>(Wqkv, wq, E3, E);
    transpose_w<<<dim3(E / 32, E / 32), dim3(32, 8)>>>(Wproj, wp, E, E);

    gemm_plain32<false><<<dim3(E3 / BN, M / BM), 256, GEMM_SMEM>>>(
        x_h, wq, bqkv, nullptr, qkv_h, E, E, E, E3, 2048, qscale);

    flash_attn<<<dim3(SEQ / 128, BATCH * N_HEAD), 256, FLASH_SMEM>>>(qkv_h, at_h);

    gemm_plain32<true><<<dim3(E / BN, M / BM), 256, GEMM_SMEM>>>(
        at_h, wp, bproj, out, nullptr, E, E, E, E, 0, 1.0f);
}